// round 2
// baseline (speedup 1.0000x reference)
#include <cuda_runtime.h>
#include <cuda_bf16.h>

#define NN 50000
#define EE 800000

// ---------------- scratch (static device globals; no allocation) ----------------
__device__ int       g_deg[3][2][NN];     // [graph][0=in,1=out]
__device__ int       g_rowptr[3][NN + 1];
__device__ int       g_cursor[3][NN];
__device__ int       g_col[3][EE];
__device__ float     g_no[3][NN];
__device__ float     g_ni[3][NN];
__device__ float     g_h[3][NN * 64];     // GEMM output (maybe no-scaled)
__device__ float     g_x[3][NN * 64];     // node feature ping-pong buffer
__device__ float     g_el[3][NN];
__device__ float     g_er[3][NN];
__device__ float     g_rosum[3][64];
__device__ unsigned  g_romax[3][64];
__device__ float     g_hsup[3][64];
__device__ float     g_elsup[3];

__device__ __forceinline__ unsigned long long fma2(unsigned long long a,
                                                   unsigned long long b,
                                                   unsigned long long c) {
    unsigned long long d;
    asm("fma.rn.f32x2 %0, %1, %2, %3;" : "=l"(d) : "l"(a), "l"(b), "l"(c));
    return d;
}

__device__ __forceinline__ float lrelu(float x) { return x > 0.f ? x : 0.2f * x; }

// ---------------- CSR build ----------------
__global__ void zero_k() {
    int i = blockIdx.x * blockDim.x + threadIdx.x;
    if (i < 3 * 2 * NN) (&g_deg[0][0][0])[i] = 0;
}

__global__ void hist_k(const int* __restrict__ s0, const int* __restrict__ d0,
                       const int* __restrict__ s1, const int* __restrict__ d1,
                       const int* __restrict__ s2, const int* __restrict__ d2) {
    int q = blockIdx.y;
    const int* S = (q == 0) ? s0 : (q == 1) ? s1 : s2;
    const int* D = (q == 0) ? d0 : (q == 1) ? d1 : d2;
    int i = blockIdx.x * blockDim.x + threadIdx.x;
    if (i < EE) {
        atomicAdd(&g_deg[q][0][D[i]], 1);
        atomicAdd(&g_deg[q][1][S[i]], 1);
    }
}

__global__ void scan_k() {
    int q = blockIdx.x, t = threadIdx.x, lane = t & 31, w = t >> 5;
    __shared__ int wsum[32];
    __shared__ int stot;
    int carry = 0;
    for (int base = 0; base < NN; base += 1024) {
        int i = base + t;
        int v = (i < NN) ? g_deg[q][0][i] : 0;
        int x = v;
        #pragma unroll
        for (int o = 1; o < 32; o <<= 1) {
            int y = __shfl_up_sync(0xffffffffu, x, o);
            if (lane >= o) x += y;
        }
        if (lane == 31) wsum[w] = x;
        __syncthreads();
        if (w == 0) {
            int s = wsum[lane], sx = s;
            #pragma unroll
            for (int o = 1; o < 32; o <<= 1) {
                int y = __shfl_up_sync(0xffffffffu, sx, o);
                if (lane >= o) sx += y;
            }
            wsum[lane] = sx - s;
            if (lane == 31) stot = sx;
        }
        __syncthreads();
        int excl = carry + wsum[w] + x - v;
        if (i < NN) { g_rowptr[q][i] = excl; g_cursor[q][i] = excl; }
        carry += stot;
        __syncthreads();
    }
    if (t == 0) g_rowptr[q][NN] = carry;
    for (int i = t; i < NN; i += 1024) {
        g_ni[q][i] = rsqrtf((float)(g_deg[q][0][i] + 1));
        g_no[q][i] = rsqrtf((float)(g_deg[q][1][i] + 1));
    }
}

__global__ void fill_k(const int* __restrict__ s0, const int* __restrict__ d0,
                       const int* __restrict__ s1, const int* __restrict__ d1,
                       const int* __restrict__ s2, const int* __restrict__ d2) {
    int q = blockIdx.y;
    const int* S = (q == 0) ? s0 : (q == 1) ? s1 : s2;
    const int* D = (q == 0) ? d0 : (q == 1) ? d1 : d2;
    int i = blockIdx.x * blockDim.x + threadIdx.x;
    if (i < EE) {
        int p = atomicAdd(&g_cursor[q][D[i]], 1);
        g_col[q][p] = S[i];
    }
}

// ---------------- GEMM: g_h[q] = X[q] @ W[q]  (optional row-scale by no[q]) ------
// tile: 32 rows x 64 cols, 256 threads, f32x2 packed math.
__global__ void __launch_bounds__(256) gemm_k(
    const float* __restrict__ X0, const float* __restrict__ X1, const float* __restrict__ X2,
    const float* __restrict__ W0, const float* __restrict__ W1, const float* __restrict__ W2,
    int srcIsGx, int useNorm, int zeroRO) {
    int q = blockIdx.y;
    const float* X = srcIsGx ? g_x[q] : ((q == 0) ? X0 : (q == 1) ? X1 : X2);
    const float* W = (q == 0) ? W0 : (q == 1) ? W1 : W2;
    __shared__ float Xs[64][66];   // Xs[k][2r] = Xs[k][2r+1] = X[row0+r][k]
    __shared__ float Ws[64][64];
    int t = threadIdx.x;
    if (zeroRO && blockIdx.x == 0 && t < 64) { g_rosum[q][t] = 0.f; g_romax[q][t] = 0u; }
    int row0 = blockIdx.x * 32;
    #pragma unroll
    for (int i = 0; i < 16; i++) {
        int idx = t + i * 256;
        Ws[idx >> 6][idx & 63] = W[idx];
    }
    #pragma unroll
    for (int i = 0; i < 8; i++) {
        int idx = t + i * 256;           // 0..2047
        int r = idx >> 6, c = idx & 63;
        int row = row0 + r;
        float v = (row < NN) ? X[row * 64 + c] : 0.f;
        Xs[c][2 * r] = v;
        Xs[c][2 * r + 1] = v;
    }
    __syncthreads();
    int cg = (t & 15) * 4;
    int rq = (t >> 4) * 2;
    unsigned long long acc00 = 0ull, acc01 = 0ull, acc10 = 0ull, acc11 = 0ull;
    #pragma unroll 8
    for (int k = 0; k < 64; k++) {
        unsigned long long x0 = *(const unsigned long long*)&Xs[k][2 * rq];
        unsigned long long x1 = *(const unsigned long long*)&Xs[k][2 * rq + 2];
        unsigned long long w0 = *(const unsigned long long*)&Ws[k][cg];
        unsigned long long w1 = *(const unsigned long long*)&Ws[k][cg + 2];
        acc00 = fma2(x0, w0, acc00);
        acc01 = fma2(x0, w1, acc01);
        acc10 = fma2(x1, w0, acc10);
        acc11 = fma2(x1, w1, acc11);
    }
    float* OUT = g_h[q];
    #pragma unroll
    for (int i = 0; i < 2; i++) {
        int row = row0 + rq + i;
        if (row < NN) {
            unsigned long long a0 = i ? acc10 : acc00;
            unsigned long long a1 = i ? acc11 : acc01;
            float o0 = __uint_as_float((unsigned)a0);
            float o1 = __uint_as_float((unsigned)(a0 >> 32));
            float o2 = __uint_as_float((unsigned)a1);
            float o3 = __uint_as_float((unsigned)(a1 >> 32));
            float s = useNorm ? g_no[q][row] : 1.f;
            float4 o = make_float4(o0 * s, o1 * s, o2 * s, o3 * s);
            *(float4*)&OUT[row * 64 + cg] = o;
        }
    }
}

// ---------------- GCN aggregation + bias + relu + readout -> g_x ----------------
__global__ void __launch_bounds__(256) gcn_agg_k(
    const float* __restrict__ b0, const float* __restrict__ b1, const float* __restrict__ b2) {
    int q = blockIdx.y;
    const float* bias = (q == 0) ? b0 : (q == 1) ? b1 : b2;
    int t = threadIdx.x, lane = t & 31, grp = t >> 5;
    int d = blockIdx.x * 8 + grp;
    const float2* __restrict__ hp = (const float2*)g_h[q];
    const int* __restrict__ col = g_col[q];
    float ox = 0.f, oy = 0.f;
    if (d < NN) {
        float2 a = hp[d * 32 + lane];   // self-loop term (already * no[d])
        float ax = a.x, ay = a.y;
        int s = g_rowptr[q][d], e = g_rowptr[q][d + 1];
        int i = s;
        for (; i + 4 <= e; i += 4) {
            int c0 = col[i], c1 = col[i + 1], c2 = col[i + 2], c3 = col[i + 3];
            float2 v0 = hp[c0 * 32 + lane];
            float2 v1 = hp[c1 * 32 + lane];
            float2 v2 = hp[c2 * 32 + lane];
            float2 v3 = hp[c3 * 32 + lane];
            ax += (v0.x + v1.x) + (v2.x + v3.x);
            ay += (v0.y + v1.y) + (v2.y + v3.y);
        }
        for (; i < e; i++) {
            int c = col[i];
            float2 v = hp[c * 32 + lane];
            ax += v.x; ay += v.y;
        }
        float ni = g_ni[q][d];
        ox = fmaxf(fmaf(ax, ni, bias[2 * lane]), 0.f);
        oy = fmaxf(fmaf(ay, ni, bias[2 * lane + 1]), 0.f);
        *(float2*)&g_x[q][d * 64 + 2 * lane] = make_float2(ox, oy);
    }
    __shared__ float ssum[8][64];
    __shared__ float smax[8][64];
    ssum[grp][2 * lane] = ox;  ssum[grp][2 * lane + 1] = oy;
    smax[grp][2 * lane] = ox;  smax[grp][2 * lane + 1] = oy;
    __syncthreads();
    if (t < 64) {
        float s = 0.f, m = 0.f;
        #pragma unroll
        for (int g2 = 0; g2 < 8; g2++) { s += ssum[g2][t]; m = fmaxf(m, smax[g2][t]); }
        atomicAdd(&g_rosum[q][t], s);
        atomicMax(&g_romax[q][t], __float_as_uint(m));  // relu output >= 0: uint order ok
    }
}

// ---------------- cross features + supernode h/el ----------------
__global__ void cross_k(const float* __restrict__ Wx, const float* __restrict__ bx,
                        const float* __restrict__ Wg, const float* __restrict__ al,
                        int rg0, int rg1, int rg2, int wk0, int wk1, int wk2) {
    int t = threadIdx.x;           // 192
    int q = t >> 6, c = t & 63;
    int rg = (q == 0) ? rg0 : (q == 1) ? rg1 : rg2;
    int wk = (q == 0) ? wk0 : (q == 1) ? wk1 : wk2;
    __shared__ float fs[3][64];
    __shared__ float red[192];
    float acc = bx[wk * 64 + c];
    const float* wp = Wx + wk * 128 * 64;
    for (int j = 0; j < 128; j++) {
        float roj = (j < 64) ? g_rosum[rg][j] * (1.f / NN)
                             : __uint_as_float(g_romax[rg][j - 64]);
        acc = fmaf(roj, wp[j * 64 + c], acc);
    }
    fs[q][c] = fmaxf(acc, 0.f);
    __syncthreads();
    float hs = 0.f;
    const float* wg = Wg + q * 4096;
    for (int k = 0; k < 64; k++) hs = fmaf(fs[q][k], wg[k * 64 + c], hs);
    g_hsup[q][c] = hs;
    red[t] = hs * al[q * 64 + c];
    for (int o = 32; o >= 1; o >>= 1) {
        __syncthreads();
        if (c < o) red[t] += red[t + o];
    }
    if (c == 0) g_elsup[q] = red[t];
}

// ---------------- per-node el/er from g_h ----------------
__global__ void __launch_bounds__(256) elr_k(const float* __restrict__ al,
                                             const float* __restrict__ ar) {
    int q = blockIdx.y;
    int t = threadIdx.x, lane = t & 31, grp = t >> 5;
    int row = blockIdx.x * 8 + grp;
    if (row >= NN) return;
    const float* h = g_h[q];
    float v0 = h[row * 64 + lane];
    float v1 = h[row * 64 + 32 + lane];
    float pl = v0 * al[q * 64 + lane] + v1 * al[q * 64 + 32 + lane];
    float pr = v0 * ar[q * 64 + lane] + v1 * ar[q * 64 + 32 + lane];
    #pragma unroll
    for (int o = 16; o; o >>= 1) {
        pl += __shfl_xor_sync(0xffffffffu, pl, o);
        pr += __shfl_xor_sync(0xffffffffu, pr, o);
    }
    if (lane == 0) { g_el[q][row] = pl; g_er[q][row] = pr; }
}

// ---------------- GAT aggregation (softmax attention) -> g_x ----------------
__global__ void __launch_bounds__(256) gat_agg_k(const float* __restrict__ bgat) {
    int q = blockIdx.y;
    int t = threadIdx.x, lane = t & 31, grp = t >> 5;
    int d = blockIdx.x * 8 + grp;
    if (d >= NN) return;
    const float* __restrict__ el = g_el[q];
    const float2* __restrict__ hp = (const float2*)g_h[q];
    const int* __restrict__ col = g_col[q];
    float erd = g_er[q][d];
    float e_self = lrelu(el[d] + erd);
    float e_sup  = lrelu(g_elsup[q] + erd);
    int s = g_rowptr[q][d], e = g_rowptr[q][d + 1];
    float m = fmaxf(e_self, e_sup);
    for (int i = s + lane; i < e; i += 32) m = fmaxf(m, lrelu(el[col[i]] + erd));
    #pragma unroll
    for (int o = 16; o; o >>= 1) m = fmaxf(m, __shfl_xor_sync(0xffffffffu, m, o));
    float ssum = 0.f, ax = 0.f, ay = 0.f;
    for (int base = s; base < e; base += 32) {
        int i = base + lane;
        int c = (i < e) ? col[i] : 0;
        float ee = (i < e) ? expf(lrelu(el[c] + erd) - m) : 0.f;
        int cnt = min(32, e - base);
        for (int j = 0; j < cnt; j++) {
            float eej = __shfl_sync(0xffffffffu, ee, j);
            int   cj  = __shfl_sync(0xffffffffu, c, j);
            float2 v = hp[cj * 32 + lane];
            ax = fmaf(eej, v.x, ax);
            ay = fmaf(eej, v.y, ay);
            ssum += eej;
        }
    }
    {   // self loop
        float ee = expf(e_self - m);
        float2 v = hp[d * 32 + lane];
        ax = fmaf(ee, v.x, ax); ay = fmaf(ee, v.y, ay); ssum += ee;
    }
    {   // supernode edge
        float ee = expf(e_sup - m);
        float2 v = *(const float2*)&g_hsup[q][2 * lane];
        ax = fmaf(ee, v.x, ax); ay = fmaf(ee, v.y, ay); ssum += ee;
    }
    float inv = 1.f / ssum;
    *(float2*)&g_x[q][d * 64 + 2 * lane] =
        make_float2(ax * inv + bgat[q * 64 + 2 * lane],
                    ay * inv + bgat[q * 64 + 2 * lane + 1]);
}

// ---------------- final MLP + log_softmax ----------------
__global__ void mlp_k(const float* __restrict__ W1, const float* __restrict__ b1,
                      const float* __restrict__ W2, const float* __restrict__ b2,
                      const float* __restrict__ W3, const float* __restrict__ b3,
                      float* __restrict__ out) {
    __shared__ float nf[384], h1[192], h2[96], z[2];
    int t = threadIdx.x;  // 384
    {
        int q = t / 128, j = t % 128;
        nf[t] = (j < 64) ? g_rosum[q][j] * (1.f / NN)
                         : __uint_as_float(g_romax[q][j - 64]);
    }
    __syncthreads();
    if (t < 192) {
        float a = b1[t];
        for (int j = 0; j < 384; j++) a = fmaf(nf[j], W1[j * 192 + t], a);
        h1[t] = fmaxf(a, 0.f);
    }
    __syncthreads();
    if (t < 96) {
        float a = b2[t];
        for (int j = 0; j < 192; j++) a = fmaf(h1[j], W2[j * 96 + t], a);
        h2[t] = fmaxf(a, 0.f);
    }
    __syncthreads();
    if (t < 2) {
        float a = b3[t];
        for (int j = 0; j < 96; j++) a = fmaf(h2[j], W3[j * 2 + t], a);
        z[t] = a;
    }
    __syncthreads();
    if (t == 0) {
        float mm = fmaxf(z[0], z[1]);
        float l = mm + logf(expf(z[0] - mm) + expf(z[1] - mm));
        out[0] = z[0] - l;
        out[1] = z[1] - l;
    }
}

// ---------------- launch ----------------
extern "C" void kernel_launch(void* const* d_in, const int* in_sizes, int n_in,
                              void* d_out, int out_size) {
    (void)in_sizes; (void)n_in; (void)out_size;
    const float* x0 = (const float*)d_in[0];
    const float* x1 = (const float*)d_in[1];
    const float* x2 = (const float*)d_in[2];
    const float* Wc[3] = {(const float*)d_in[3], (const float*)d_in[5], (const float*)d_in[7]};
    const float* bc[3] = {(const float*)d_in[4], (const float*)d_in[6], (const float*)d_in[8]};
    const float* Wx   = (const float*)d_in[9];
    const float* bx   = (const float*)d_in[10];
    const float* Wgat = (const float*)d_in[11];
    const float* al   = (const float*)d_in[12];
    const float* ar   = (const float*)d_in[13];
    const float* bgat = (const float*)d_in[14];
    const float* W1 = (const float*)d_in[15];
    const float* b1 = (const float*)d_in[16];
    const float* W2 = (const float*)d_in[17];
    const float* b2 = (const float*)d_in[18];
    const float* W3 = (const float*)d_in[19];
    const float* b3 = (const float*)d_in[20];
    const int* s0 = (const int*)d_in[21];
    const int* d0 = (const int*)d_in[22];
    const int* s1 = (const int*)d_in[23];
    const int* d1 = (const int*)d_in[24];
    const int* s2 = (const int*)d_in[25];
    const int* d2 = (const int*)d_in[26];
    float* out = (float*)d_out;

    // CSR build
    zero_k<<<(3 * 2 * NN + 255) / 256, 256>>>();
    dim3 ge((EE + 255) / 256, 3);
    hist_k<<<ge, 256>>>(s0, d0, s1, d1, s2, d2);
    scan_k<<<3, 1024>>>();
    fill_k<<<ge, 256>>>(s0, d0, s1, d1, s2, d2);

    dim3 gg((NN + 31) / 32, 3);   // gemm
    dim3 ga((NN + 7) / 8, 3);     // per-node warp kernels

    // ---- iteration 0 ----
    gemm_k<<<gg, 256>>>(x0, x1, x2, Wc[0], Wc[1], Wc[2], 0, 1, 1);
    gcn_agg_k<<<ga, 256>>>(bc[0], bc[1], bc[2]);
    // it=0: s_f<-gro(Wx1), g_f<-tro(Wx0), t_f<-sro(Wx2)
    cross_k<<<1, 192>>>(Wx, bx, Wgat, al, 1, 2, 0, 1, 0, 2);
    gemm_k<<<gg, 256>>>(nullptr, nullptr, nullptr, Wgat, Wgat + 4096, Wgat + 8192, 1, 0, 0);
    elr_k<<<ga, 256>>>(al, ar);
    gat_agg_k<<<ga, 256>>>(bgat);

    // ---- iteration 1 ----
    gemm_k<<<gg, 256>>>(nullptr, nullptr, nullptr,
                        Wc[0] + 4096, Wc[1] + 4096, Wc[2] + 4096, 1, 1, 1);
    gcn_agg_k<<<ga, 256>>>(bc[0] + 64, bc[1] + 64, bc[2] + 64);
    // it=1: s_f<-tro(Wx5), g_f<-sro(Wx3), t_f<-gro(Wx4)
    cross_k<<<1, 192>>>(Wx, bx, Wgat, al, 2, 0, 1, 5, 3, 4);
    gemm_k<<<gg, 256>>>(nullptr, nullptr, nullptr, Wgat, Wgat + 4096, Wgat + 8192, 1, 0, 0);
    elr_k<<<ga, 256>>>(al, ar);
    gat_agg_k<<<ga, 256>>>(bgat);

    // ---- final layer ----
    gemm_k<<<gg, 256>>>(nullptr, nullptr, nullptr,
                        Wc[0] + 8192, Wc[1] + 8192, Wc[2] + 8192, 1, 1, 1);
    gcn_agg_k<<<ga, 256>>>(bc[0] + 128, bc[1] + 128, bc[2] + 128);
    mlp_k<<<1, 384>>>(W1, b1, W2, b2, W3, b3, out);
}

// round 3
// speedup vs baseline: 1.0560x; 1.0560x over previous
#include <cuda_runtime.h>
#include <cuda_bf16.h>

#define NN 50000
#define EE 800000

// ---------------- scratch (static device globals; no allocation) ----------------
__device__ int       g_deg[3][2][NN];     // [graph][0=in,1=out]
__device__ int       g_rowptr[3][NN + 1];
__device__ int       g_cursor[3][NN];
__device__ int       g_col[3][EE];
__device__ float     g_no[3][NN];
__device__ float     g_ni[3][NN];
__device__ float     g_h[3][NN * 64];     // GEMM output (maybe no-scaled)
__device__ float     g_x[3][NN * 64];     // node feature ping-pong buffer
__device__ float     g_el[3][NN];
__device__ float     g_er[3][NN];
__device__ float     g_rosum[3][64];
__device__ unsigned  g_romax[3][64];
__device__ float     g_hsup[3][64];
__device__ float     g_elsup[3];

__device__ __forceinline__ unsigned long long fma2(unsigned long long a,
                                                   unsigned long long b,
                                                   unsigned long long c) {
    unsigned long long d;
    asm("fma.rn.f32x2 %0, %1, %2, %3;" : "=l"(d) : "l"(a), "l"(b), "l"(c));
    return d;
}

__device__ __forceinline__ float lrelu(float x) { return x > 0.f ? x : 0.2f * x; }

// ---------------- CSR build ----------------
__global__ void zero_k() {
    int i = blockIdx.x * blockDim.x + threadIdx.x;
    if (i < 3 * 2 * NN) (&g_deg[0][0][0])[i] = 0;
}

__global__ void hist_k(const int* __restrict__ s0, const int* __restrict__ d0,
                       const int* __restrict__ s1, const int* __restrict__ d1,
                       const int* __restrict__ s2, const int* __restrict__ d2) {
    int q = blockIdx.y;
    const int* S = (q == 0) ? s0 : (q == 1) ? s1 : s2;
    const int* D = (q == 0) ? d0 : (q == 1) ? d1 : d2;
    int i = blockIdx.x * blockDim.x + threadIdx.x;
    if (i < EE) {
        atomicAdd(&g_deg[q][0][D[i]], 1);
        atomicAdd(&g_deg[q][1][S[i]], 1);
    }
}

__global__ void scan_k() {
    int q = blockIdx.x, t = threadIdx.x, lane = t & 31, w = t >> 5;
    __shared__ int wsum[32];
    __shared__ int stot;
    int carry = 0;
    for (int base = 0; base < NN; base += 1024) {
        int i = base + t;
        int v = (i < NN) ? g_deg[q][0][i] : 0;
        int x = v;
        #pragma unroll
        for (int o = 1; o < 32; o <<= 1) {
            int y = __shfl_up_sync(0xffffffffu, x, o);
            if (lane >= o) x += y;
        }
        if (lane == 31) wsum[w] = x;
        __syncthreads();
        if (w == 0) {
            int s = wsum[lane], sx = s;
            #pragma unroll
            for (int o = 1; o < 32; o <<= 1) {
                int y = __shfl_up_sync(0xffffffffu, sx, o);
                if (lane >= o) sx += y;
            }
            wsum[lane] = sx - s;
            if (lane == 31) stot = sx;
        }
        __syncthreads();
        int excl = carry + wsum[w] + x - v;
        if (i < NN) { g_rowptr[q][i] = excl; g_cursor[q][i] = excl; }
        carry += stot;
        __syncthreads();
    }
    if (t == 0) g_rowptr[q][NN] = carry;
    for (int i = t; i < NN; i += 1024) {
        g_ni[q][i] = rsqrtf((float)(g_deg[q][0][i] + 1));
        g_no[q][i] = rsqrtf((float)(g_deg[q][1][i] + 1));
    }
}

__global__ void fill_k(const int* __restrict__ s0, const int* __restrict__ d0,
                       const int* __restrict__ s1, const int* __restrict__ d1,
                       const int* __restrict__ s2, const int* __restrict__ d2) {
    int q = blockIdx.y;
    const int* S = (q == 0) ? s0 : (q == 1) ? s1 : s2;
    const int* D = (q == 0) ? d0 : (q == 1) ? d1 : d2;
    int i = blockIdx.x * blockDim.x + threadIdx.x;
    if (i < EE) {
        int p = atomicAdd(&g_cursor[q][D[i]], 1);
        g_col[q][p] = S[i];
    }
}

// ---------------- GEMM: g_h[q] = X[q] @ W[q] ------------------------------------
// tile: 32 rows x 64 cols, 256 threads, f32x2 packed math.
// useNorm: scale rows by no[q][row]. doEl: also emit el/er = h @ {al,ar}.
__global__ void __launch_bounds__(256) gemm_k(
    const float* __restrict__ X0, const float* __restrict__ X1, const float* __restrict__ X2,
    const float* __restrict__ W0, const float* __restrict__ W1, const float* __restrict__ W2,
    const float* __restrict__ al, const float* __restrict__ ar,
    int srcIsGx, int useNorm, int zeroRO, int doEl) {
    int q = blockIdx.y;
    const float* X = srcIsGx ? g_x[q] : ((q == 0) ? X0 : (q == 1) ? X1 : X2);
    const float* W = (q == 0) ? W0 : (q == 1) ? W1 : W2;
    __shared__ float Xs[64][66];   // Xs[k][2r] = Xs[k][2r+1] = X[row0+r][k]
    __shared__ float Ws[64][64];
    int t = threadIdx.x;
    if (zeroRO && blockIdx.x == 0 && t < 64) { g_rosum[q][t] = 0.f; g_romax[q][t] = 0u; }
    int row0 = blockIdx.x * 32;
    #pragma unroll
    for (int i = 0; i < 16; i++) {
        int idx = t + i * 256;
        Ws[idx >> 6][idx & 63] = W[idx];
    }
    #pragma unroll
    for (int i = 0; i < 8; i++) {
        int idx = t + i * 256;           // 0..2047
        int r = idx >> 6, c = idx & 63;
        int row = row0 + r;
        float v = (row < NN) ? X[row * 64 + c] : 0.f;
        Xs[c][2 * r] = v;
        Xs[c][2 * r + 1] = v;
    }
    __syncthreads();
    int cg = (t & 15) * 4;
    int rq = (t >> 4) * 2;
    unsigned long long acc00 = 0ull, acc01 = 0ull, acc10 = 0ull, acc11 = 0ull;
    #pragma unroll 8
    for (int k = 0; k < 64; k++) {
        unsigned long long x0 = *(const unsigned long long*)&Xs[k][2 * rq];
        unsigned long long x1 = *(const unsigned long long*)&Xs[k][2 * rq + 2];
        unsigned long long w0 = *(const unsigned long long*)&Ws[k][cg];
        unsigned long long w1 = *(const unsigned long long*)&Ws[k][cg + 2];
        acc00 = fma2(x0, w0, acc00);
        acc01 = fma2(x0, w1, acc01);
        acc10 = fma2(x1, w0, acc10);
        acc11 = fma2(x1, w1, acc11);
    }
    float al0 = 0.f, al1 = 0.f, al2 = 0.f, al3 = 0.f;
    float ar0 = 0.f, ar1 = 0.f, ar2 = 0.f, ar3 = 0.f;
    if (doEl) {
        const float* alq = al + q * 64;
        const float* arq = ar + q * 64;
        al0 = alq[cg]; al1 = alq[cg + 1]; al2 = alq[cg + 2]; al3 = alq[cg + 3];
        ar0 = arq[cg]; ar1 = arq[cg + 1]; ar2 = arq[cg + 2]; ar3 = arq[cg + 3];
    }
    float* OUT = g_h[q];
    #pragma unroll
    for (int i = 0; i < 2; i++) {
        int row = row0 + rq + i;
        unsigned long long a0 = i ? acc10 : acc00;
        unsigned long long a1 = i ? acc11 : acc01;
        float o0 = __uint_as_float((unsigned)a0);
        float o1 = __uint_as_float((unsigned)(a0 >> 32));
        float o2 = __uint_as_float((unsigned)a1);
        float o3 = __uint_as_float((unsigned)(a1 >> 32));
        if (row < NN) {
            float s = useNorm ? g_no[q][row] : 1.f;
            float4 o = make_float4(o0 * s, o1 * s, o2 * s, o3 * s);
            *(float4*)&OUT[row * 64 + cg] = o;
        }
        if (doEl) {
            float pl = o0 * al0 + o1 * al1 + o2 * al2 + o3 * al3;
            float pr = o0 * ar0 + o1 * ar1 + o2 * ar2 + o3 * ar3;
            #pragma unroll
            for (int o5 = 8; o5; o5 >>= 1) {
                pl += __shfl_xor_sync(0xffffffffu, pl, o5, 16);
                pr += __shfl_xor_sync(0xffffffffu, pr, o5, 16);
            }
            if ((t & 15) == 0 && row < NN) { g_el[q][row] = pl; g_er[q][row] = pr; }
        }
    }
}

// ---------------- GCN aggregation + bias + relu + readout -> g_x ----------------
__global__ void __launch_bounds__(256) gcn_agg_k(
    const float* __restrict__ b0, const float* __restrict__ b1, const float* __restrict__ b2,
    int writeX) {
    int q = blockIdx.y;
    const float* bias = (q == 0) ? b0 : (q == 1) ? b1 : b2;
    int t = threadIdx.x, lane = t & 31, grp = t >> 5;
    int d = blockIdx.x * 8 + grp;
    const float2* __restrict__ hp = (const float2*)g_h[q];
    const int* __restrict__ col = g_col[q];
    float ox = 0.f, oy = 0.f;
    if (d < NN) {
        float2 a = hp[d * 32 + lane];   // self-loop term (already * no[d])
        float ax = a.x, ay = a.y;
        int s = g_rowptr[q][d], e = g_rowptr[q][d + 1];
        int i = s;
        for (; i + 4 <= e; i += 4) {
            int c0 = col[i], c1 = col[i + 1], c2 = col[i + 2], c3 = col[i + 3];
            float2 v0 = hp[c0 * 32 + lane];
            float2 v1 = hp[c1 * 32 + lane];
            float2 v2 = hp[c2 * 32 + lane];
            float2 v3 = hp[c3 * 32 + lane];
            ax += (v0.x + v1.x) + (v2.x + v3.x);
            ay += (v0.y + v1.y) + (v2.y + v3.y);
        }
        for (; i < e; i++) {
            int c = col[i];
            float2 v = hp[c * 32 + lane];
            ax += v.x; ay += v.y;
        }
        float ni = g_ni[q][d];
        ox = fmaxf(fmaf(ax, ni, bias[2 * lane]), 0.f);
        oy = fmaxf(fmaf(ay, ni, bias[2 * lane + 1]), 0.f);
        if (writeX)
            *(float2*)&g_x[q][d * 64 + 2 * lane] = make_float2(ox, oy);
    }
    __shared__ float ssum[8][64];
    __shared__ float smax[8][64];
    ssum[grp][2 * lane] = ox;  ssum[grp][2 * lane + 1] = oy;
    smax[grp][2 * lane] = ox;  smax[grp][2 * lane + 1] = oy;
    __syncthreads();
    if (t < 64) {
        float s = 0.f, m = 0.f;
        #pragma unroll
        for (int g2 = 0; g2 < 8; g2++) { s += ssum[g2][t]; m = fmaxf(m, smax[g2][t]); }
        atomicAdd(&g_rosum[q][t], s);
        atomicMax(&g_romax[q][t], __float_as_uint(m));  // relu output >= 0: uint order ok
    }
}

// ---------------- cross features + supernode h/el ----------------
__global__ void cross_k(const float* __restrict__ Wx, const float* __restrict__ bx,
                        const float* __restrict__ Wg, const float* __restrict__ al,
                        int rg0, int rg1, int rg2, int wk0, int wk1, int wk2) {
    int t = threadIdx.x;           // 192
    int q = t >> 6, c = t & 63;
    int rg = (q == 0) ? rg0 : (q == 1) ? rg1 : rg2;
    int wk = (q == 0) ? wk0 : (q == 1) ? wk1 : wk2;
    __shared__ float fs[3][64];
    __shared__ float red[192];
    float acc = bx[wk * 64 + c];
    const float* wp = Wx + wk * 128 * 64;
    for (int j = 0; j < 128; j++) {
        float roj = (j < 64) ? g_rosum[rg][j] * (1.f / NN)
                             : __uint_as_float(g_romax[rg][j - 64]);
        acc = fmaf(roj, wp[j * 64 + c], acc);
    }
    fs[q][c] = fmaxf(acc, 0.f);
    __syncthreads();
    float hs = 0.f;
    const float* wg = Wg + q * 4096;
    for (int k = 0; k < 64; k++) hs = fmaf(fs[q][k], wg[k * 64 + c], hs);
    g_hsup[q][c] = hs;
    red[t] = hs * al[q * 64 + c];
    for (int o = 32; o >= 1; o >>= 1) {
        __syncthreads();
        if (c < o) red[t] += red[t + o];
    }
    if (c == 0) g_elsup[q] = red[t];
}

// ---------------- GAT aggregation: online softmax, single edge pass -> g_x ------
__global__ void __launch_bounds__(256) gat_agg_k(const float* __restrict__ bgat) {
    int q = blockIdx.y;
    int t = threadIdx.x, lane = t & 31, grp = t >> 5;
    int d = blockIdx.x * 8 + grp;
    __shared__ float sh_ee[8][32];
    __shared__ int   sh_c[8][32];
    if (d >= NN) return;
    const float* __restrict__ el = g_el[q];
    const float2* __restrict__ hp = (const float2*)g_h[q];
    const int* __restrict__ col = g_col[q];
    float erd = g_er[q][d];
    float e_self = lrelu(el[d] + erd);
    float e_sup  = lrelu(g_elsup[q] + erd);
    int s = g_rowptr[q][d], e = g_rowptr[q][d + 1];
    float m = -1e30f, ssum = 0.f, ax = 0.f, ay = 0.f;
    for (int base = s; base < e; base += 32) {
        int i = base + lane;
        int cnt = min(32, e - base);
        int c = (i < e) ? col[i] : 0;
        float ei = (i < e) ? lrelu(el[c] + erd) : -1e30f;
        float cm = ei;
        #pragma unroll
        for (int o = 16; o; o >>= 1) cm = fmaxf(cm, __shfl_xor_sync(0xffffffffu, cm, o));
        float m2 = fmaxf(m, cm);
        float sc = expf(m - m2);
        ax *= sc; ay *= sc; ssum *= sc;
        m = m2;
        __syncwarp();
        sh_ee[grp][lane] = (i < e) ? expf(ei - m2) : 0.f;
        sh_c[grp][lane] = c;
        __syncwarp();
        int j = 0;
        for (; j + 4 <= cnt; j += 4) {
            float e0 = sh_ee[grp][j],     e1 = sh_ee[grp][j + 1];
            float e2 = sh_ee[grp][j + 2], e3 = sh_ee[grp][j + 3];
            int c0 = sh_c[grp][j],     c1 = sh_c[grp][j + 1];
            int c2 = sh_c[grp][j + 2], c3 = sh_c[grp][j + 3];
            float2 v0 = hp[c0 * 32 + lane];
            float2 v1 = hp[c1 * 32 + lane];
            float2 v2 = hp[c2 * 32 + lane];
            float2 v3 = hp[c3 * 32 + lane];
            ax = fmaf(e0, v0.x, fmaf(e1, v1.x, fmaf(e2, v2.x, fmaf(e3, v3.x, ax))));
            ay = fmaf(e0, v0.y, fmaf(e1, v1.y, fmaf(e2, v2.y, fmaf(e3, v3.y, ay))));
            ssum += (e0 + e1) + (e2 + e3);
        }
        for (; j < cnt; j++) {
            float e0 = sh_ee[grp][j];
            int c0 = sh_c[grp][j];
            float2 v0 = hp[c0 * 32 + lane];
            ax = fmaf(e0, v0.x, ax);
            ay = fmaf(e0, v0.y, ay);
            ssum += e0;
        }
    }
    // fold self-loop + supernode edge
    float m2 = fmaxf(m, fmaxf(e_self, e_sup));
    float sc = expf(m - m2);
    ax *= sc; ay *= sc; ssum *= sc;
    {
        float ee = expf(e_self - m2);
        float2 v = hp[d * 32 + lane];
        ax = fmaf(ee, v.x, ax); ay = fmaf(ee, v.y, ay); ssum += ee;
    }
    {
        float ee = expf(e_sup - m2);
        float2 v = *(const float2*)&g_hsup[q][2 * lane];
        ax = fmaf(ee, v.x, ax); ay = fmaf(ee, v.y, ay); ssum += ee;
    }
    float inv = 1.f / ssum;
    *(float2*)&g_x[q][d * 64 + 2 * lane] =
        make_float2(ax * inv + bgat[q * 64 + 2 * lane],
                    ay * inv + bgat[q * 64 + 2 * lane + 1]);
}

// ---------------- final MLP + log_softmax ----------------
__global__ void mlp_k(const float* __restrict__ W1, const float* __restrict__ b1,
                      const float* __restrict__ W2, const float* __restrict__ b2,
                      const float* __restrict__ W3, const float* __restrict__ b3,
                      float* __restrict__ out) {
    __shared__ float nf[384], h1[192], h2[96], z[2];
    int t = threadIdx.x;  // 384
    {
        int q = t / 128, j = t % 128;
        nf[t] = (j < 64) ? g_rosum[q][j] * (1.f / NN)
                         : __uint_as_float(g_romax[q][j - 64]);
    }
    __syncthreads();
    if (t < 192) {
        float a = b1[t];
        for (int j = 0; j < 384; j++) a = fmaf(nf[j], W1[j * 192 + t], a);
        h1[t] = fmaxf(a, 0.f);
    }
    __syncthreads();
    if (t < 96) {
        float a = b2[t];
        for (int j = 0; j < 192; j++) a = fmaf(h1[j], W2[j * 96 + t], a);
        h2[t] = fmaxf(a, 0.f);
    }
    __syncthreads();
    if (t < 2) {
        float a = b3[t];
        for (int j = 0; j < 96; j++) a = fmaf(h2[j], W3[j * 2 + t], a);
        z[t] = a;
    }
    __syncthreads();
    if (t == 0) {
        float mm = fmaxf(z[0], z[1]);
        float l = mm + logf(expf(z[0] - mm) + expf(z[1] - mm));
        out[0] = z[0] - l;
        out[1] = z[1] - l;
    }
}

// ---------------- launch ----------------
extern "C" void kernel_launch(void* const* d_in, const int* in_sizes, int n_in,
                              void* d_out, int out_size) {
    (void)in_sizes; (void)n_in; (void)out_size;
    const float* x0 = (const float*)d_in[0];
    const float* x1 = (const float*)d_in[1];
    const float* x2 = (const float*)d_in[2];
    const float* Wc[3] = {(const float*)d_in[3], (const float*)d_in[5], (const float*)d_in[7]};
    const float* bc[3] = {(const float*)d_in[4], (const float*)d_in[6], (const float*)d_in[8]};
    const float* Wx   = (const float*)d_in[9];
    const float* bx   = (const float*)d_in[10];
    const float* Wgat = (const float*)d_in[11];
    const float* al   = (const float*)d_in[12];
    const float* ar   = (const float*)d_in[13];
    const float* bgat = (const float*)d_in[14];
    const float* W1 = (const float*)d_in[15];
    const float* b1 = (const float*)d_in[16];
    const float* W2 = (const float*)d_in[17];
    const float* b2 = (const float*)d_in[18];
    const float* W3 = (const float*)d_in[19];
    const float* b3 = (const float*)d_in[20];
    const int* s0 = (const int*)d_in[21];
    const int* d0 = (const int*)d_in[22];
    const int* s1 = (const int*)d_in[23];
    const int* d1 = (const int*)d_in[24];
    const int* s2 = (const int*)d_in[25];
    const int* d2 = (const int*)d_in[26];
    float* out = (float*)d_out;

    // CSR build
    zero_k<<<(3 * 2 * NN + 255) / 256, 256>>>();
    dim3 ge((EE + 255) / 256, 3);
    hist_k<<<ge, 256>>>(s0, d0, s1, d1, s2, d2);
    scan_k<<<3, 1024>>>();
    fill_k<<<ge, 256>>>(s0, d0, s1, d1, s2, d2);

    dim3 gg((NN + 31) / 32, 3);   // gemm
    dim3 ga((NN + 7) / 8, 3);     // per-node warp kernels

    // ---- iteration 0 ----
    gemm_k<<<gg, 256>>>(x0, x1, x2, Wc[0], Wc[1], Wc[2], nullptr, nullptr, 0, 1, 1, 0);
    gcn_agg_k<<<ga, 256>>>(bc[0], bc[1], bc[2], 1);
    // it=0: s_f<-gro(Wx1), g_f<-tro(Wx0), t_f<-sro(Wx2)
    cross_k<<<1, 192>>>(Wx, bx, Wgat, al, 1, 2, 0, 1, 0, 2);
    gemm_k<<<gg, 256>>>(nullptr, nullptr, nullptr,
                        Wgat, Wgat + 4096, Wgat + 8192, al, ar, 1, 0, 0, 1);
    gat_agg_k<<<ga, 256>>>(bgat);

    // ---- iteration 1 ----
    gemm_k<<<gg, 256>>>(nullptr, nullptr, nullptr,
                        Wc[0] + 4096, Wc[1] + 4096, Wc[2] + 4096, nullptr, nullptr, 1, 1, 1, 0);
    gcn_agg_k<<<ga, 256>>>(bc[0] + 64, bc[1] + 64, bc[2] + 64, 1);
    // it=1: s_f<-tro(Wx5), g_f<-sro(Wx3), t_f<-gro(Wx4)
    cross_k<<<1, 192>>>(Wx, bx, Wgat, al, 2, 0, 1, 5, 3, 4);
    gemm_k<<<gg, 256>>>(nullptr, nullptr, nullptr,
                        Wgat, Wgat + 4096, Wgat + 8192, al, ar, 1, 0, 0, 1);
    gat_agg_k<<<ga, 256>>>(bgat);

    // ---- final layer (readout only; no g_x write) ----
    gemm_k<<<gg, 256>>>(nullptr, nullptr, nullptr,
                        Wc[0] + 8192, Wc[1] + 8192, Wc[2] + 8192, nullptr, nullptr, 1, 1, 1, 0);
    gcn_agg_k<<<ga, 256>>>(bc[0] + 128, bc[1] + 128, bc[2] + 128, 0);
    mlp_k<<<1, 384>>>(W1, b1, W2, b2, W3, b3, out);
}

// round 4
// speedup vs baseline: 1.0784x; 1.0211x over previous
#include <cuda_runtime.h>
#include <cuda_fp16.h>

#define NN 50000
#define EE 800000

// ---------------- scratch (static device globals; no allocation) ----------------
__device__ int       g_deg[3][2][NN];     // [graph][0=in,1=out]  (returned to 0 by scan_k)
__device__ int       g_rowptr[3][NN + 1];
__device__ int       g_cursor[3][NN];
__device__ int       g_col[3][EE];
__device__ float     g_no[3][NN];
__device__ float     g_ni[3][NN];
__device__ __half    g_h[3][NN * 64];     // GEMM output, fp16 (gather source)
__device__ float     g_x[3][NN * 64];     // node feature ping-pong buffer (fp32)
__device__ float     g_el[3][NN];
__device__ float     g_er[3][NN];
__device__ float     g_rosum[3][64];
__device__ unsigned  g_romax[3][64];
__device__ float     g_hsup[3][64];
__device__ float     g_elsup[3];

__device__ __forceinline__ unsigned long long fma2(unsigned long long a,
                                                   unsigned long long b,
                                                   unsigned long long c) {
    unsigned long long d;
    asm("fma.rn.f32x2 %0, %1, %2, %3;" : "=l"(d) : "l"(a), "l"(b), "l"(c));
    return d;
}

__device__ __forceinline__ float lrelu(float x) { return x > 0.f ? x : 0.2f * x; }

// ---------------- CSR build ----------------
__global__ void hist_k(const int* __restrict__ s0, const int* __restrict__ d0,
                       const int* __restrict__ s1, const int* __restrict__ d1,
                       const int* __restrict__ s2, const int* __restrict__ d2) {
    int q = blockIdx.y;
    const int* S = (q == 0) ? s0 : (q == 1) ? s1 : s2;
    const int* D = (q == 0) ? d0 : (q == 1) ? d1 : d2;
    int i = blockIdx.x * blockDim.x + threadIdx.x;
    if (i < EE) {
        atomicAdd(&g_deg[q][0][D[i]], 1);
        atomicAdd(&g_deg[q][1][S[i]], 1);
    }
}

__global__ void scan_k() {
    int q = blockIdx.x, t = threadIdx.x, lane = t & 31, w = t >> 5;
    __shared__ int wsum[32];
    __shared__ int stot;
    int carry = 0;
    for (int base = 0; base < NN; base += 1024) {
        int i = base + t;
        int v = (i < NN) ? g_deg[q][0][i] : 0;
        int x = v;
        #pragma unroll
        for (int o = 1; o < 32; o <<= 1) {
            int y = __shfl_up_sync(0xffffffffu, x, o);
            if (lane >= o) x += y;
        }
        if (lane == 31) wsum[w] = x;
        __syncthreads();
        if (w == 0) {
            int s = wsum[lane], sx = s;
            #pragma unroll
            for (int o = 1; o < 32; o <<= 1) {
                int y = __shfl_up_sync(0xffffffffu, sx, o);
                if (lane >= o) sx += y;
            }
            wsum[lane] = sx - s;
            if (lane == 31) stot = sx;
        }
        __syncthreads();
        int excl = carry + wsum[w] + x - v;
        if (i < NN) { g_rowptr[q][i] = excl; g_cursor[q][i] = excl; }
        carry += stot;
        __syncthreads();
    }
    if (t == 0) g_rowptr[q][NN] = carry;
    // ni/no + restore deg to zero for the next replay (each element owned by one thread)
    for (int i = t; i < NN; i += 1024) {
        int di = g_deg[q][0][i], dq = g_deg[q][1][i];
        g_ni[q][i] = rsqrtf((float)(di + 1));
        g_no[q][i] = rsqrtf((float)(dq + 1));
        g_deg[q][0][i] = 0;
        g_deg[q][1][i] = 0;
    }
}

__global__ void fill_k(const int* __restrict__ s0, const int* __restrict__ d0,
                       const int* __restrict__ s1, const int* __restrict__ d1,
                       const int* __restrict__ s2, const int* __restrict__ d2) {
    int q = blockIdx.y;
    const int* S = (q == 0) ? s0 : (q == 1) ? s1 : s2;
    const int* D = (q == 0) ? d0 : (q == 1) ? d1 : d2;
    int i = blockIdx.x * blockDim.x + threadIdx.x;
    if (i < EE) {
        int p = atomicAdd(&g_cursor[q][D[i]], 1);
        g_col[q][p] = S[i];
    }
}

// ---------------- GEMM: g_h[q] = fp16( (X[q] @ W[q]) * optional no ) -------------
// tile: 32 rows x 64 cols, 256 threads, f32x2 packed math.
// doEl: also emit el/er = h @ {al,ar} (from fp32 registers, pre-quantization).
__global__ void __launch_bounds__(256) gemm_k(
    const float* __restrict__ X0, const float* __restrict__ X1, const float* __restrict__ X2,
    const float* __restrict__ W0, const float* __restrict__ W1, const float* __restrict__ W2,
    const float* __restrict__ al, const float* __restrict__ ar,
    int srcIsGx, int useNorm, int zeroRO, int doEl) {
    int q = blockIdx.y;
    const float* X = srcIsGx ? g_x[q] : ((q == 0) ? X0 : (q == 1) ? X1 : X2);
    const float* W = (q == 0) ? W0 : (q == 1) ? W1 : W2;
    __shared__ float Xs[64][66];   // Xs[k][2r] = Xs[k][2r+1] = X[row0+r][k]
    __shared__ float Ws[64][64];
    int t = threadIdx.x;
    if (zeroRO && blockIdx.x == 0 && t < 64) { g_rosum[q][t] = 0.f; g_romax[q][t] = 0u; }
    int row0 = blockIdx.x * 32;
    #pragma unroll
    for (int i = 0; i < 16; i++) {
        int idx = t + i * 256;
        Ws[idx >> 6][idx & 63] = W[idx];
    }
    #pragma unroll
    for (int i = 0; i < 8; i++) {
        int idx = t + i * 256;           // 0..2047
        int r = idx >> 6, c = idx & 63;
        int row = row0 + r;
        float v = (row < NN) ? X[row * 64 + c] : 0.f;
        Xs[c][2 * r] = v;
        Xs[c][2 * r + 1] = v;
    }
    __syncthreads();
    int cg = (t & 15) * 4;
    int rq = (t >> 4) * 2;
    unsigned long long acc00 = 0ull, acc01 = 0ull, acc10 = 0ull, acc11 = 0ull;
    #pragma unroll 8
    for (int k = 0; k < 64; k++) {
        unsigned long long x0 = *(const unsigned long long*)&Xs[k][2 * rq];
        unsigned long long x1 = *(const unsigned long long*)&Xs[k][2 * rq + 2];
        unsigned long long w0 = *(const unsigned long long*)&Ws[k][cg];
        unsigned long long w1 = *(const unsigned long long*)&Ws[k][cg + 2];
        acc00 = fma2(x0, w0, acc00);
        acc01 = fma2(x0, w1, acc01);
        acc10 = fma2(x1, w0, acc10);
        acc11 = fma2(x1, w1, acc11);
    }
    float al0 = 0.f, al1 = 0.f, al2 = 0.f, al3 = 0.f;
    float ar0 = 0.f, ar1 = 0.f, ar2 = 0.f, ar3 = 0.f;
    if (doEl) {
        const float* alq = al + q * 64;
        const float* arq = ar + q * 64;
        al0 = alq[cg]; al1 = alq[cg + 1]; al2 = alq[cg + 2]; al3 = alq[cg + 3];
        ar0 = arq[cg]; ar1 = arq[cg + 1]; ar2 = arq[cg + 2]; ar3 = arq[cg + 3];
    }
    __half* OUT = g_h[q];
    #pragma unroll
    for (int i = 0; i < 2; i++) {
        int row = row0 + rq + i;
        unsigned long long a0 = i ? acc10 : acc00;
        unsigned long long a1 = i ? acc11 : acc01;
        float o0 = __uint_as_float((unsigned)a0);
        float o1 = __uint_as_float((unsigned)(a0 >> 32));
        float o2 = __uint_as_float((unsigned)a1);
        float o3 = __uint_as_float((unsigned)(a1 >> 32));
        if (row < NN) {
            float s = useNorm ? g_no[q][row] : 1.f;
            __half2 p0 = __floats2half2_rn(o0 * s, o1 * s);
            __half2 p1 = __floats2half2_rn(o2 * s, o3 * s);
            uint2 pk = make_uint2(*(unsigned*)&p0, *(unsigned*)&p1);
            *(uint2*)&OUT[row * 64 + cg] = pk;
        }
        if (doEl) {
            float pl = o0 * al0 + o1 * al1 + o2 * al2 + o3 * al3;
            float pr = o0 * ar0 + o1 * ar1 + o2 * ar2 + o3 * ar3;
            #pragma unroll
            for (int o5 = 8; o5; o5 >>= 1) {
                pl += __shfl_xor_sync(0xffffffffu, pl, o5, 16);
                pr += __shfl_xor_sync(0xffffffffu, pr, o5, 16);
            }
            if ((t & 15) == 0 && row < NN) { g_el[q][row] = pl; g_er[q][row] = pr; }
        }
    }
}

// ---------------- GCN aggregation + bias + relu + readout -> g_x ----------------
__global__ void __launch_bounds__(256) gcn_agg_k(
    const float* __restrict__ b0, const float* __restrict__ b1, const float* __restrict__ b2,
    int writeX) {
    int q = blockIdx.y;
    const float* bias = (q == 0) ? b0 : (q == 1) ? b1 : b2;
    int t = threadIdx.x, lane = t & 31, grp = t >> 5;
    int d = blockIdx.x * 8 + grp;
    const __half2* __restrict__ hp = (const __half2*)g_h[q];
    const int* __restrict__ col = g_col[q];
    float ox = 0.f, oy = 0.f;
    if (d < NN) {
        float2 a = __half22float2(hp[d * 32 + lane]);   // self-loop (already * no[d])
        float ax = a.x, ay = a.y;
        int s = g_rowptr[q][d], e = g_rowptr[q][d + 1];
        int i = s;
        for (; i + 8 <= e; i += 8) {
            int c0 = col[i],     c1 = col[i + 1], c2 = col[i + 2], c3 = col[i + 3];
            int c4 = col[i + 4], c5 = col[i + 5], c6 = col[i + 6], c7 = col[i + 7];
            float2 v0 = __half22float2(hp[c0 * 32 + lane]);
            float2 v1 = __half22float2(hp[c1 * 32 + lane]);
            float2 v2 = __half22float2(hp[c2 * 32 + lane]);
            float2 v3 = __half22float2(hp[c3 * 32 + lane]);
            float2 v4 = __half22float2(hp[c4 * 32 + lane]);
            float2 v5 = __half22float2(hp[c5 * 32 + lane]);
            float2 v6 = __half22float2(hp[c6 * 32 + lane]);
            float2 v7 = __half22float2(hp[c7 * 32 + lane]);
            ax += ((v0.x + v1.x) + (v2.x + v3.x)) + ((v4.x + v5.x) + (v6.x + v7.x));
            ay += ((v0.y + v1.y) + (v2.y + v3.y)) + ((v4.y + v5.y) + (v6.y + v7.y));
        }
        for (; i < e; i++) {
            int c = col[i];
            float2 v = __half22float2(hp[c * 32 + lane]);
            ax += v.x; ay += v.y;
        }
        float ni = g_ni[q][d];
        ox = fmaxf(fmaf(ax, ni, bias[2 * lane]), 0.f);
        oy = fmaxf(fmaf(ay, ni, bias[2 * lane + 1]), 0.f);
        if (writeX)
            *(float2*)&g_x[q][d * 64 + 2 * lane] = make_float2(ox, oy);
    }
    __shared__ float ssum[8][64];
    __shared__ float smax[8][64];
    ssum[grp][2 * lane] = ox;  ssum[grp][2 * lane + 1] = oy;
    smax[grp][2 * lane] = ox;  smax[grp][2 * lane + 1] = oy;
    __syncthreads();
    if (t < 64) {
        float s = 0.f, m = 0.f;
        #pragma unroll
        for (int g2 = 0; g2 < 8; g2++) { s += ssum[g2][t]; m = fmaxf(m, smax[g2][t]); }
        atomicAdd(&g_rosum[q][t], s);
        atomicMax(&g_romax[q][t], __float_as_uint(m));  // relu output >= 0: uint order ok
    }
}

// ---------------- cross features + supernode h/el ----------------
__global__ void cross_k(const float* __restrict__ Wx, const float* __restrict__ bx,
                        const float* __restrict__ Wg, const float* __restrict__ al,
                        int rg0, int rg1, int rg2, int wk0, int wk1, int wk2) {
    int t = threadIdx.x;           // 192
    int q = t >> 6, c = t & 63;
    int rg = (q == 0) ? rg0 : (q == 1) ? rg1 : rg2;
    int wk = (q == 0) ? wk0 : (q == 1) ? wk1 : wk2;
    __shared__ float fs[3][64];
    __shared__ float red[192];
    float acc = bx[wk * 64 + c];
    const float* wp = Wx + wk * 128 * 64;
    for (int j = 0; j < 128; j++) {
        float roj = (j < 64) ? g_rosum[rg][j] * (1.f / NN)
                             : __uint_as_float(g_romax[rg][j - 64]);
        acc = fmaf(roj, wp[j * 64 + c], acc);
    }
    fs[q][c] = fmaxf(acc, 0.f);
    __syncthreads();
    float hs = 0.f;
    const float* wg = Wg + q * 4096;
    for (int k = 0; k < 64; k++) hs = fmaf(fs[q][k], wg[k * 64 + c], hs);
    g_hsup[q][c] = hs;
    red[t] = hs * al[q * 64 + c];
    for (int o = 32; o >= 1; o >>= 1) {
        __syncthreads();
        if (c < o) red[t] += red[t + o];
    }
    if (c == 0) g_elsup[q] = red[t];
}

// ---------------- GAT aggregation: online softmax, single edge pass -> g_x ------
__global__ void __launch_bounds__(256) gat_agg_k(const float* __restrict__ bgat) {
    int q = blockIdx.y;
    int t = threadIdx.x, lane = t & 31, grp = t >> 5;
    int d = blockIdx.x * 8 + grp;
    __shared__ float sh_ee[8][32];
    __shared__ int   sh_c[8][32];
    if (d >= NN) return;
    const float* __restrict__ el = g_el[q];
    const __half2* __restrict__ hp = (const __half2*)g_h[q];
    const int* __restrict__ col = g_col[q];
    float erd = g_er[q][d];
    float e_self = lrelu(el[d] + erd);
    float e_sup  = lrelu(g_elsup[q] + erd);
    int s = g_rowptr[q][d], e = g_rowptr[q][d + 1];
    float m = -1e30f, ssum = 0.f, ax = 0.f, ay = 0.f;
    for (int base = s; base < e; base += 32) {
        int i = base + lane;
        int cnt = min(32, e - base);
        int c = (i < e) ? col[i] : 0;
        float ei = (i < e) ? lrelu(el[c] + erd) : -1e30f;
        float cm = ei;
        #pragma unroll
        for (int o = 16; o; o >>= 1) cm = fmaxf(cm, __shfl_xor_sync(0xffffffffu, cm, o));
        float m2 = fmaxf(m, cm);
        float sc = expf(m - m2);
        ax *= sc; ay *= sc; ssum *= sc;
        m = m2;
        __syncwarp();
        sh_ee[grp][lane] = (i < e) ? expf(ei - m2) : 0.f;
        sh_c[grp][lane] = c;
        __syncwarp();
        int j = 0;
        for (; j + 4 <= cnt; j += 4) {
            float e0 = sh_ee[grp][j],     e1 = sh_ee[grp][j + 1];
            float e2 = sh_ee[grp][j + 2], e3 = sh_ee[grp][j + 3];
            int c0 = sh_c[grp][j],     c1 = sh_c[grp][j + 1];
            int c2 = sh_c[grp][j + 2], c3 = sh_c[grp][j + 3];
            float2 v0 = __half22float2(hp[c0 * 32 + lane]);
            float2 v1 = __half22float2(hp[c1 * 32 + lane]);
            float2 v2 = __half22float2(hp[c2 * 32 + lane]);
            float2 v3 = __half22float2(hp[c3 * 32 + lane]);
            ax = fmaf(e0, v0.x, fmaf(e1, v1.x, fmaf(e2, v2.x, fmaf(e3, v3.x, ax))));
            ay = fmaf(e0, v0.y, fmaf(e1, v1.y, fmaf(e2, v2.y, fmaf(e3, v3.y, ay))));
            ssum += (e0 + e1) + (e2 + e3);
        }
        for (; j < cnt; j++) {
            float e0 = sh_ee[grp][j];
            int c0 = sh_c[grp][j];
            float2 v0 = __half22float2(hp[c0 * 32 + lane]);
            ax = fmaf(e0, v0.x, ax);
            ay = fmaf(e0, v0.y, ay);
            ssum += e0;
        }
    }
    // fold self-loop + supernode edge
    float m2 = fmaxf(m, fmaxf(e_self, e_sup));
    float sc = expf(m - m2);
    ax *= sc; ay *= sc; ssum *= sc;
    {
        float ee = expf(e_self - m2);
        float2 v = __half22float2(hp[d * 32 + lane]);
        ax = fmaf(ee, v.x, ax); ay = fmaf(ee, v.y, ay); ssum += ee;
    }
    {
        float ee = expf(e_sup - m2);
        float2 v = *(const float2*)&g_hsup[q][2 * lane];
        ax = fmaf(ee, v.x, ax); ay = fmaf(ee, v.y, ay); ssum += ee;
    }
    float inv = 1.f / ssum;
    *(float2*)&g_x[q][d * 64 + 2 * lane] =
        make_float2(ax * inv + bgat[q * 64 + 2 * lane],
                    ay * inv + bgat[q * 64 + 2 * lane + 1]);
}

// ---------------- final MLP + log_softmax ----------------
__global__ void mlp_k(const float* __restrict__ W1, const float* __restrict__ b1,
                      const float* __restrict__ W2, const float* __restrict__ b2,
                      const float* __restrict__ W3, const float* __restrict__ b3,
                      float* __restrict__ out) {
    __shared__ float nf[384], h1[192], h2[96], z[2];
    int t = threadIdx.x;  // 384
    {
        int q = t / 128, j = t % 128;
        nf[t] = (j < 64) ? g_rosum[q][j] * (1.f / NN)
                         : __uint_as_float(g_romax[q][j - 64]);
    }
    __syncthreads();
    if (t < 192) {
        float a = b1[t];
        for (int j = 0; j < 384; j++) a = fmaf(nf[j], W1[j * 192 + t], a);
        h1[t] = fmaxf(a, 0.f);
    }
    __syncthreads();
    if (t < 96) {
        float a = b2[t];
        for (int j = 0; j < 192; j++) a = fmaf(h1[j], W2[j * 96 + t], a);
        h2[t] = fmaxf(a, 0.f);
    }
    __syncthreads();
    if (t < 2) {
        float a = b3[t];
        for (int j = 0; j < 96; j++) a = fmaf(h2[j], W3[j * 2 + t], a);
        z[t] = a;
    }
    __syncthreads();
    if (t == 0) {
        float mm = fmaxf(z[0], z[1]);
        float l = mm + logf(expf(z[0] - mm) + expf(z[1] - mm));
        out[0] = z[0] - l;
        out[1] = z[1] - l;
    }
}

// ---------------- launch ----------------
extern "C" void kernel_launch(void* const* d_in, const int* in_sizes, int n_in,
                              void* d_out, int out_size) {
    (void)in_sizes; (void)n_in; (void)out_size;
    const float* x0 = (const float*)d_in[0];
    const float* x1 = (const float*)d_in[1];
    const float* x2 = (const float*)d_in[2];
    const float* Wc[3] = {(const float*)d_in[3], (const float*)d_in[5], (const float*)d_in[7]};
    const float* bc[3] = {(const float*)d_in[4], (const float*)d_in[6], (const float*)d_in[8]};
    const float* Wx   = (const float*)d_in[9];
    const float* bx   = (const float*)d_in[10];
    const float* Wgat = (const float*)d_in[11];
    const float* al   = (const float*)d_in[12];
    const float* ar   = (const float*)d_in[13];
    const float* bgat = (const float*)d_in[14];
    const float* W1 = (const float*)d_in[15];
    const float* b1 = (const float*)d_in[16];
    const float* W2 = (const float*)d_in[17];
    const float* b2 = (const float*)d_in[18];
    const float* W3 = (const float*)d_in[19];
    const float* b3 = (const float*)d_in[20];
    const int* s0 = (const int*)d_in[21];
    const int* d0 = (const int*)d_in[22];
    const int* s1 = (const int*)d_in[23];
    const int* d1 = (const int*)d_in[24];
    const int* s2 = (const int*)d_in[25];
    const int* d2 = (const int*)d_in[26];
    float* out = (float*)d_out;

    // CSR build (g_deg restored to zero by scan_k each call)
    dim3 ge((EE + 255) / 256, 3);
    hist_k<<<ge, 256>>>(s0, d0, s1, d1, s2, d2);
    scan_k<<<3, 1024>>>();
    fill_k<<<ge, 256>>>(s0, d0, s1, d1, s2, d2);

    dim3 gg((NN + 31) / 32, 3);   // gemm
    dim3 ga((NN + 7) / 8, 3);     // per-node warp kernels

    // ---- iteration 0 ----
    gemm_k<<<gg, 256>>>(x0, x1, x2, Wc[0], Wc[1], Wc[2], nullptr, nullptr, 0, 1, 1, 0);
    gcn_agg_k<<<ga, 256>>>(bc[0], bc[1], bc[2], 1);
    // it=0: s_f<-gro(Wx1), g_f<-tro(Wx0), t_f<-sro(Wx2)
    cross_k<<<1, 192>>>(Wx, bx, Wgat, al, 1, 2, 0, 1, 0, 2);
    gemm_k<<<gg, 256>>>(nullptr, nullptr, nullptr,
                        Wgat, Wgat + 4096, Wgat + 8192, al, ar, 1, 0, 0, 1);
    gat_agg_k<<<ga, 256>>>(bgat);

    // ---- iteration 1 ----
    gemm_k<<<gg, 256>>>(nullptr, nullptr, nullptr,
                        Wc[0] + 4096, Wc[1] + 4096, Wc[2] + 4096, nullptr, nullptr, 1, 1, 1, 0);
    gcn_agg_k<<<ga, 256>>>(bc[0] + 64, bc[1] + 64, bc[2] + 64, 1);
    // it=1: s_f<-tro(Wx5), g_f<-sro(Wx3), t_f<-gro(Wx4)
    cross_k<<<1, 192>>>(Wx, bx, Wgat, al, 2, 0, 1, 5, 3, 4);
    gemm_k<<<gg, 256>>>(nullptr, nullptr, nullptr,
                        Wgat, Wgat + 4096, Wgat + 8192, al, ar, 1, 0, 0, 1);
    gat_agg_k<<<ga, 256>>>(bgat);

    // ---- final layer (readout only; no g_x write) ----
    gemm_k<<<gg, 256>>>(nullptr, nullptr, nullptr,
                        Wc[0] + 8192, Wc[1] + 8192, Wc[2] + 8192, nullptr, nullptr, 1, 1, 1, 0);
    gcn_agg_k<<<ga, 256>>>(bc[0] + 128, bc[1] + 128, bc[2] + 128, 0);
    mlp_k<<<1, 384>>>(W1, b1, W2, b2, W3, b3, out);
}

// round 6
// speedup vs baseline: 1.2839x; 1.1906x over previous
#include <cuda_runtime.h>
#include <cuda_fp16.h>

#define NN 50000
#define EE 800000

typedef unsigned long long u64;

// ---------------- scratch (static device globals; no allocation) ----------------
__device__ int       g_deg[3][2][NN];     // [graph][0=in,1=out]  (returned to 0 by scan_k)
__device__ int       g_rowptr[3][NN + 1];
__device__ int       g_cursor[3][NN];
__device__ int       g_col[3][EE];
__device__ float     g_no[3][NN];
__device__ float     g_ni[3][NN];
__device__ __half    g_h[3][NN * 64];     // GEMM output, fp16 (gather source)
__device__ float     g_x[3][NN * 64];     // node feature ping-pong buffer (fp32)
__device__ float     g_el[3][NN];
__device__ float     g_er[3][NN];
__device__ float     g_rosum[3][64];
__device__ unsigned  g_romax[3][64];
__device__ float     g_hsup[3][64];
__device__ float     g_elsup[3];

__device__ __forceinline__ u64 fma2(u64 a, u64 b, u64 c) {
    u64 d;
    asm("fma.rn.f32x2 %0, %1, %2, %3;" : "=l"(d) : "l"(a), "l"(b), "l"(c));
    return d;
}
__device__ __forceinline__ u64 dupf(float w) {
    u64 r;
    asm("mov.b64 %0, {%1, %1};" : "=l"(r) : "f"(w));
    return r;
}
__device__ __forceinline__ float f2lo(u64 v) { return __uint_as_float((unsigned)v); }
__device__ __forceinline__ float f2hi(u64 v) { return __uint_as_float((unsigned)(v >> 32)); }

__device__ __forceinline__ float lrelu(float x) { return x > 0.f ? x : 0.2f * x; }

// ---------------- CSR build ----------------
__global__ void hist_k(const int* __restrict__ s0, const int* __restrict__ d0,
                       const int* __restrict__ s1, const int* __restrict__ d1,
                       const int* __restrict__ s2, const int* __restrict__ d2) {
    int q = blockIdx.y;
    const int* S = (q == 0) ? s0 : (q == 1) ? s1 : s2;
    const int* D = (q == 0) ? d0 : (q == 1) ? d1 : d2;
    int i = blockIdx.x * blockDim.x + threadIdx.x;
    if (i < EE) {
        atomicAdd(&g_deg[q][0][D[i]], 1);
        atomicAdd(&g_deg[q][1][S[i]], 1);
    }
}

__global__ void scan_k() {
    int q = blockIdx.x, t = threadIdx.x, lane = t & 31, w = t >> 5;
    __shared__ int wsum[32];
    __shared__ int stot;
    int carry = 0;
    for (int base = 0; base < NN; base += 1024) {
        int i = base + t;
        int v = (i < NN) ? g_deg[q][0][i] : 0;
        int x = v;
        #pragma unroll
        for (int o = 1; o < 32; o <<= 1) {
            int y = __shfl_up_sync(0xffffffffu, x, o);
            if (lane >= o) x += y;
        }
        if (lane == 31) wsum[w] = x;
        __syncthreads();
        if (w == 0) {
            int s = wsum[lane], sx = s;
            #pragma unroll
            for (int o = 1; o < 32; o <<= 1) {
                int y = __shfl_up_sync(0xffffffffu, sx, o);
                if (lane >= o) sx += y;
            }
            wsum[lane] = sx - s;
            if (lane == 31) stot = sx;
        }
        __syncthreads();
        int excl = carry + wsum[w] + x - v;
        if (i < NN) { g_rowptr[q][i] = excl; g_cursor[q][i] = excl; }
        carry += stot;
        __syncthreads();
    }
    if (t == 0) g_rowptr[q][NN] = carry;
    // ni/no + restore deg to zero for the next replay (each element owned by one thread)
    for (int i = t; i < NN; i += 1024) {
        int di = g_deg[q][0][i], dq = g_deg[q][1][i];
        g_ni[q][i] = rsqrtf((float)(di + 1));
        g_no[q][i] = rsqrtf((float)(dq + 1));
        g_deg[q][0][i] = 0;
        g_deg[q][1][i] = 0;
    }
}

__global__ void fill_k(const int* __restrict__ s0, const int* __restrict__ d0,
                       const int* __restrict__ s1, const int* __restrict__ d1,
                       const int* __restrict__ s2, const int* __restrict__ d2) {
    int q = blockIdx.y;
    const int* S = (q == 0) ? s0 : (q == 1) ? s1 : s2;
    const int* D = (q == 0) ? d0 : (q == 1) ? d1 : d2;
    int i = blockIdx.x * blockDim.x + threadIdx.x;
    if (i < EE) {
        int p = atomicAdd(&g_cursor[q][D[i]], 1);
        g_col[q][p] = S[i];
    }
}

// ---------------- GEMM: g_h[q] = fp16( (X[q] @ W[q]) * optional no ) -------------
// 128 threads, block tile 128 rows x 64 cols, thread tile 8x8, f32x2 row-pair accs.
__global__ void __launch_bounds__(128) gemm_k(
    const float* __restrict__ X0, const float* __restrict__ X1, const float* __restrict__ X2,
    const float* __restrict__ W0, const float* __restrict__ W1, const float* __restrict__ W2,
    const float* __restrict__ al, const float* __restrict__ ar,
    int srcIsGx, int useNorm, int zeroRO, int doEl) {
    int q = blockIdx.y;
    const float* X = srcIsGx ? g_x[q] : ((q == 0) ? X0 : (q == 1) ? X1 : X2);
    const float* W = (q == 0) ? W0 : (q == 1) ? W1 : W2;
    __shared__ float Xs[64][130];   // [k][row] transposed, 128 rows + pad
    __shared__ float Ws[64][64];    // [k][col]
    int t = threadIdx.x;
    if (zeroRO && blockIdx.x == 0 && t < 64) { g_rosum[q][t] = 0.f; g_romax[q][t] = 0u; }
    int row0 = blockIdx.x * 128;
    // load W (flat 4096 floats = 1024 float4)
    #pragma unroll
    for (int i = 0; i < 8; i++) {
        int idx = t + i * 128;                 // float4 index 0..1023
        float4 wv = *(const float4*)&W[idx * 4];
        int k = (idx * 4) >> 6, c = (idx * 4) & 63;
        *(float4*)&Ws[k][c] = wv;
    }
    // load X tile (2048 float4), transpose into Xs
    #pragma unroll
    for (int i = 0; i < 16; i++) {
        int idx = t + i * 128;                 // 0..2047
        int r = idx >> 4, k4 = idx & 15;       // row 0..127, k-quad 0..15
        int row = row0 + r;
        float4 v = (row < NN) ? *(const float4*)&X[row * 64 + k4 * 4]
                              : make_float4(0.f, 0.f, 0.f, 0.f);
        Xs[k4 * 4 + 0][r] = v.x;
        Xs[k4 * 4 + 1][r] = v.y;
        Xs[k4 * 4 + 2][r] = v.z;
        Xs[k4 * 4 + 3][r] = v.w;
    }
    __syncthreads();

    int tx = t & 7;          // col group: cols c0..c0+7
    int ty = t >> 3;         // row group: rows r0..r0+7
    int c0 = tx * 8;
    int r0 = ty * 8;
    u64 acc[4][8];
    #pragma unroll
    for (int j = 0; j < 4; j++)
        #pragma unroll
        for (int c = 0; c < 8; c++) acc[j][c] = 0ull;

    #pragma unroll 8
    for (int k = 0; k < 64; k++) {
        u64 x0 = *(const u64*)&Xs[k][r0];
        u64 x1 = *(const u64*)&Xs[k][r0 + 2];
        u64 x2 = *(const u64*)&Xs[k][r0 + 4];
        u64 x3 = *(const u64*)&Xs[k][r0 + 6];
        float4 wa = *(const float4*)&Ws[k][c0];
        float4 wb = *(const float4*)&Ws[k][c0 + 4];
        u64 wd[8];
        wd[0] = dupf(wa.x); wd[1] = dupf(wa.y); wd[2] = dupf(wa.z); wd[3] = dupf(wa.w);
        wd[4] = dupf(wb.x); wd[5] = dupf(wb.y); wd[6] = dupf(wb.z); wd[7] = dupf(wb.w);
        #pragma unroll
        for (int c = 0; c < 8; c++) {
            acc[0][c] = fma2(x0, wd[c], acc[0][c]);
            acc[1][c] = fma2(x1, wd[c], acc[1][c]);
            acc[2][c] = fma2(x2, wd[c], acc[2][c]);
            acc[3][c] = fma2(x3, wd[c], acc[3][c]);
        }
    }

    int rbase = row0 + r0;
    // optional per-row norm scale
    float s[8];
    #pragma unroll
    for (int e = 0; e < 8; e++) s[e] = 1.f;
    if (useNorm) {
        #pragma unroll
        for (int e = 0; e < 8; e++) {
            int row = rbase + e;
            s[e] = (row < NN) ? g_no[q][row] : 1.f;
        }
    }
    __half* OUT = g_h[q];
    #pragma unroll
    for (int j = 0; j < 4; j++) {
        int rA = rbase + 2 * j, rB = rA + 1;
        if (rA < NN) {
            float sA = s[2 * j];
            __half2 p0 = __floats2half2_rn(f2lo(acc[j][0]) * sA, f2lo(acc[j][1]) * sA);
            __half2 p1 = __floats2half2_rn(f2lo(acc[j][2]) * sA, f2lo(acc[j][3]) * sA);
            __half2 p2 = __floats2half2_rn(f2lo(acc[j][4]) * sA, f2lo(acc[j][5]) * sA);
            __half2 p3 = __floats2half2_rn(f2lo(acc[j][6]) * sA, f2lo(acc[j][7]) * sA);
            uint4 pk = make_uint4(*(unsigned*)&p0, *(unsigned*)&p1,
                                  *(unsigned*)&p2, *(unsigned*)&p3);
            *(uint4*)&OUT[rA * 64 + c0] = pk;
        }
        if (rB < NN) {
            float sB = s[2 * j + 1];
            __half2 p0 = __floats2half2_rn(f2hi(acc[j][0]) * sB, f2hi(acc[j][1]) * sB);
            __half2 p1 = __floats2half2_rn(f2hi(acc[j][2]) * sB, f2hi(acc[j][3]) * sB);
            __half2 p2 = __floats2half2_rn(f2hi(acc[j][4]) * sB, f2hi(acc[j][5]) * sB);
            __half2 p3 = __floats2half2_rn(f2hi(acc[j][6]) * sB, f2hi(acc[j][7]) * sB);
            uint4 pk = make_uint4(*(unsigned*)&p0, *(unsigned*)&p1,
                                  *(unsigned*)&p2, *(unsigned*)&p3);
            *(uint4*)&OUT[rB * 64 + c0] = pk;
        }
    }
    if (doEl) {
        const float* alq = al + q * 64;
        const float* arq = ar + q * 64;
        float4 ala = *(const float4*)&alq[c0];
        float4 alb = *(const float4*)&alq[c0 + 4];
        float4 ara = *(const float4*)&arq[c0];
        float4 arb = *(const float4*)&arq[c0 + 4];
        float alv[8] = {ala.x, ala.y, ala.z, ala.w, alb.x, alb.y, alb.z, alb.w};
        float arv[8] = {ara.x, ara.y, ara.z, ara.w, arb.x, arb.y, arb.z, arb.w};
        #pragma unroll
        for (int j = 0; j < 4; j++) {
            u64 pl = 0ull, pr = 0ull;
            #pragma unroll
            for (int c = 0; c < 8; c++) {
                pl = fma2(acc[j][c], dupf(alv[c]), pl);
                pr = fma2(acc[j][c], dupf(arv[c]), pr);
            }
            float pl0 = f2lo(pl), pl1 = f2hi(pl);
            float pr0 = f2lo(pr), pr1 = f2hi(pr);
            #pragma unroll
            for (int o = 4; o; o >>= 1) {
                pl0 += __shfl_xor_sync(0xffffffffu, pl0, o, 8);
                pl1 += __shfl_xor_sync(0xffffffffu, pl1, o, 8);
                pr0 += __shfl_xor_sync(0xffffffffu, pr0, o, 8);
                pr1 += __shfl_xor_sync(0xffffffffu, pr1, o, 8);
            }
            int rA = rbase + 2 * j, rB = rA + 1;
            if (tx == 0) {
                if (rA < NN) { g_el[q][rA] = pl0; g_er[q][rA] = pr0; }
                if (rB < NN) { g_el[q][rB] = pl1; g_er[q][rB] = pr1; }
            }
        }
    }
}

// ---------------- GCN aggregation + bias + relu + readout -> g_x ----------------
__global__ void __launch_bounds__(256) gcn_agg_k(
    const float* __restrict__ b0, const float* __restrict__ b1, const float* __restrict__ b2,
    int writeX) {
    int q = blockIdx.y;
    const float* bias = (q == 0) ? b0 : (q == 1) ? b1 : b2;
    int t = threadIdx.x, lane = t & 31, grp = t >> 5;
    int d = blockIdx.x * 8 + grp;
    const __half2* __restrict__ hp = (const __half2*)g_h[q];
    const int* __restrict__ col = g_col[q];
    float ox = 0.f, oy = 0.f;
    if (d < NN) {
        float2 a = __half22float2(hp[d * 32 + lane]);   // self-loop (already * no[d])
        float ax = a.x, ay = a.y;
        int s = g_rowptr[q][d], e = g_rowptr[q][d + 1];
        int i = s;
        for (; i + 8 <= e; i += 8) {
            int c0 = col[i],     c1 = col[i + 1], c2 = col[i + 2], c3 = col[i + 3];
            int c4 = col[i + 4], c5 = col[i + 5], c6 = col[i + 6], c7 = col[i + 7];
            float2 v0 = __half22float2(hp[c0 * 32 + lane]);
            float2 v1 = __half22float2(hp[c1 * 32 + lane]);
            float2 v2 = __half22float2(hp[c2 * 32 + lane]);
            float2 v3 = __half22float2(hp[c3 * 32 + lane]);
            float2 v4 = __half22float2(hp[c4 * 32 + lane]);
            float2 v5 = __half22float2(hp[c5 * 32 + lane]);
            float2 v6 = __half22float2(hp[c6 * 32 + lane]);
            float2 v7 = __half22float2(hp[c7 * 32 + lane]);
            ax += ((v0.x + v1.x) + (v2.x + v3.x)) + ((v4.x + v5.x) + (v6.x + v7.x));
            ay += ((v0.y + v1.y) + (v2.y + v3.y)) + ((v4.y + v5.y) + (v6.y + v7.y));
        }
        for (; i < e; i++) {
            int c = col[i];
            float2 v = __half22float2(hp[c * 32 + lane]);
            ax += v.x; ay += v.y;
        }
        float ni = g_ni[q][d];
        ox = fmaxf(fmaf(ax, ni, bias[2 * lane]), 0.f);
        oy = fmaxf(fmaf(ay, ni, bias[2 * lane + 1]), 0.f);
        if (writeX)
            *(float2*)&g_x[q][d * 64 + 2 * lane] = make_float2(ox, oy);
    }
    __shared__ float ssum[8][64];
    __shared__ float smax[8][64];
    ssum[grp][2 * lane] = ox;  ssum[grp][2 * lane + 1] = oy;
    smax[grp][2 * lane] = ox;  smax[grp][2 * lane + 1] = oy;
    __syncthreads();
    if (t < 64) {
        float s = 0.f, m = 0.f;
        #pragma unroll
        for (int g2 = 0; g2 < 8; g2++) { s += ssum[g2][t]; m = fmaxf(m, smax[g2][t]); }
        atomicAdd(&g_rosum[q][t], s);
        atomicMax(&g_romax[q][t], __float_as_uint(m));  // relu output >= 0: uint order ok
    }
}

// ---------------- cross features + supernode h/el ----------------
__global__ void cross_k(const float* __restrict__ Wx, const float* __restrict__ bx,
                        const float* __restrict__ Wg, const float* __restrict__ al,
                        int rg0, int rg1, int rg2, int wk0, int wk1, int wk2) {
    int t = threadIdx.x;           // 192
    int q = t >> 6, c = t & 63;
    int rg = (q == 0) ? rg0 : (q == 1) ? rg1 : rg2;
    int wk = (q == 0) ? wk0 : (q == 1) ? wk1 : wk2;
    __shared__ float fs[3][64];
    __shared__ float red[192];
    float acc = bx[wk * 64 + c];
    const float* wp = Wx + wk * 128 * 64;
    for (int j = 0; j < 128; j++) {
        float roj = (j < 64) ? g_rosum[rg][j] * (1.f / NN)
                             : __uint_as_float(g_romax[rg][j - 64]);
        acc = fmaf(roj, wp[j * 64 + c], acc);
    }
    fs[q][c] = fmaxf(acc, 0.f);
    __syncthreads();
    float hs = 0.f;
    const float* wg = Wg + q * 4096;
    for (int k = 0; k < 64; k++) hs = fmaf(fs[q][k], wg[k * 64 + c], hs);
    g_hsup[q][c] = hs;
    red[t] = hs * al[q * 64 + c];
    for (int o = 32; o >= 1; o >>= 1) {
        __syncthreads();
        if (c < o) red[t] += red[t + o];
    }
    if (c == 0) g_elsup[q] = red[t];
}

// ---------------- GAT aggregation: online softmax, single edge pass -> g_x ------
__global__ void __launch_bounds__(256) gat_agg_k(const float* __restrict__ bgat) {
    int q = blockIdx.y;
    int t = threadIdx.x, lane = t & 31, grp = t >> 5;
    int d = blockIdx.x * 8 + grp;
    __shared__ float sh_ee[8][32];
    __shared__ int   sh_c[8][32];
    if (d >= NN) return;
    const float* __restrict__ el = g_el[q];
    const __half2* __restrict__ hp = (const __half2*)g_h[q];
    const int* __restrict__ col = g_col[q];
    float erd = g_er[q][d];
    float e_self = lrelu(el[d] + erd);
    float e_sup  = lrelu(g_elsup[q] + erd);
    int s = g_rowptr[q][d], e = g_rowptr[q][d + 1];
    float m = -1e30f, ssum = 0.f, ax = 0.f, ay = 0.f;
    for (int base = s; base < e; base += 32) {
        int i = base + lane;
        int cnt = min(32, e - base);
        int c = (i < e) ? col[i] : 0;
        float ei = (i < e) ? lrelu(el[c] + erd) : -1e30f;
        float cm = ei;
        #pragma unroll
        for (int o = 16; o; o >>= 1) cm = fmaxf(cm, __shfl_xor_sync(0xffffffffu, cm, o));
        float m2 = fmaxf(m, cm);
        float sc = expf(m - m2);
        ax *= sc; ay *= sc; ssum *= sc;
        m = m2;
        __syncwarp();
        sh_ee[grp][lane] = (i < e) ? expf(ei - m2) : 0.f;
        sh_c[grp][lane] = c;
        __syncwarp();
        int j = 0;
        for (; j + 4 <= cnt; j += 4) {
            float e0 = sh_ee[grp][j],     e1 = sh_ee[grp][j + 1];
            float e2 = sh_ee[grp][j + 2], e3 = sh_ee[grp][j + 3];
            int c0 = sh_c[grp][j],     c1 = sh_c[grp][j + 1];
            int c2 = sh_c[grp][j + 2], c3 = sh_c[grp][j + 3];
            float2 v0 = __half22float2(hp[c0 * 32 + lane]);
            float2 v1 = __half22float2(hp[c1 * 32 + lane]);
            float2 v2 = __half22float2(hp[c2 * 32 + lane]);
            float2 v3 = __half22float2(hp[c3 * 32 + lane]);
            ax = fmaf(e0, v0.x, fmaf(e1, v1.x, fmaf(e2, v2.x, fmaf(e3, v3.x, ax))));
            ay = fmaf(e0, v0.y, fmaf(e1, v1.y, fmaf(e2, v2.y, fmaf(e3, v3.y, ay))));
            ssum += (e0 + e1) + (e2 + e3);
        }
        for (; j < cnt; j++) {
            float e0 = sh_ee[grp][j];
            int c0 = sh_c[grp][j];
            float2 v0 = __half22float2(hp[c0 * 32 + lane]);
            ax = fmaf(e0, v0.x, ax);
            ay = fmaf(e0, v0.y, ay);
            ssum += e0;
        }
    }
    // fold self-loop + supernode edge
    float m2 = fmaxf(m, fmaxf(e_self, e_sup));
    float sc = expf(m - m2);
    ax *= sc; ay *= sc; ssum *= sc;
    {
        float ee = expf(e_self - m2);
        float2 v = __half22float2(hp[d * 32 + lane]);
        ax = fmaf(ee, v.x, ax); ay = fmaf(ee, v.y, ay); ssum += ee;
    }
    {
        float ee = expf(e_sup - m2);
        float2 v = *(const float2*)&g_hsup[q][2 * lane];
        ax = fmaf(ee, v.x, ax); ay = fmaf(ee, v.y, ay); ssum += ee;
    }
    float inv = 1.f / ssum;
    *(float2*)&g_x[q][d * 64 + 2 * lane] =
        make_float2(ax * inv + bgat[q * 64 + 2 * lane],
                    ay * inv + bgat[q * 64 + 2 * lane + 1]);
}

// ---------------- final MLP + log_softmax ----------------
__global__ void mlp_k(const float* __restrict__ W1, const float* __restrict__ b1,
                      const float* __restrict__ W2, const float* __restrict__ b2,
                      const float* __restrict__ W3, const float* __restrict__ b3,
                      float* __restrict__ out) {
    __shared__ float nf[384], h1[192], h2[96], z[2];
    int t = threadIdx.x;  // 384
    {
        int q = t / 128, j = t % 128;
        nf[t] = (j < 64) ? g_rosum[q][j] * (1.f / NN)
                         : __uint_as_float(g_romax[q][j - 64]);
    }
    __syncthreads();
    if (t < 192) {
        float a = b1[t];
        for (int j = 0; j < 384; j++) a = fmaf(nf[j], W1[j * 192 + t], a);
        h1[t] = fmaxf(a, 0.f);
    }
    __syncthreads();
    if (t < 96) {
        float a = b2[t];
        for (int j = 0; j < 192; j++) a = fmaf(h1[j], W2[j * 96 + t], a);
        h2[t] = fmaxf(a, 0.f);
    }
    __syncthreads();
    if (t < 2) {
        float a = b3[t];
        for (int j = 0; j < 96; j++) a = fmaf(h2[j], W3[j * 2 + t], a);
        z[t] = a;
    }
    __syncthreads();
    if (t == 0) {
        float mm = fmaxf(z[0], z[1]);
        float l = mm + logf(expf(z[0] - mm) + expf(z[1] - mm));
        out[0] = z[0] - l;
        out[1] = z[1] - l;
    }
}

// ---------------- launch ----------------
extern "C" void kernel_launch(void* const* d_in, const int* in_sizes, int n_in,
                              void* d_out, int out_size) {
    (void)in_sizes; (void)n_in; (void)out_size;
    const float* x0 = (const float*)d_in[0];
    const float* x1 = (const float*)d_in[1];
    const float* x2 = (const float*)d_in[2];
    const float* Wc[3] = {(const float*)d_in[3], (const float*)d_in[5], (const float*)d_in[7]};
    const float* bc[3] = {(const float*)d_in[4], (const float*)d_in[6], (const float*)d_in[8]};
    const float* Wx   = (const float*)d_in[9];
    const float* bx   = (const float*)d_in[10];
    const float* Wgat = (const float*)d_in[11];
    const float* al   = (const float*)d_in[12];
    const float* ar   = (const float*)d_in[13];
    const float* bgat = (const float*)d_in[14];
    const float* W1 = (const float*)d_in[15];
    const float* b1 = (const float*)d_in[16];
    const float* W2 = (const float*)d_in[17];
    const float* b2 = (const float*)d_in[18];
    const float* W3 = (const float*)d_in[19];
    const float* b3 = (const float*)d_in[20];
    const int* s0 = (const int*)d_in[21];
    const int* d0 = (const int*)d_in[22];
    const int* s1 = (const int*)d_in[23];
    const int* d1 = (const int*)d_in[24];
    const int* s2 = (const int*)d_in[25];
    const int* d2 = (const int*)d_in[26];
    float* out = (float*)d_out;

    // CSR build (g_deg restored to zero by scan_k each call)
    dim3 ge((EE + 255) / 256, 3);
    hist_k<<<ge, 256>>>(s0, d0, s1, d1, s2, d2);
    scan_k<<<3, 1024>>>();
    fill_k<<<ge, 256>>>(s0, d0, s1, d1, s2, d2);

    dim3 gg((NN + 127) / 128, 3);   // gemm (128-row tiles)
    dim3 ga((NN + 7) / 8, 3);       // per-node warp kernels

    // ---- iteration 0 ----
    gemm_k<<<gg, 128>>>(x0, x1, x2, Wc[0], Wc[1], Wc[2], nullptr, nullptr, 0, 1, 1, 0);
    gcn_agg_k<<<ga, 256>>>(bc[0], bc[1], bc[2], 1);
    // it=0: s_f<-gro(Wx1), g_f<-tro(Wx0), t_f<-sro(Wx2)
    cross_k<<<1, 192>>>(Wx, bx, Wgat, al, 1, 2, 0, 1, 0, 2);
    gemm_k<<<gg, 128>>>(nullptr, nullptr, nullptr,
                        Wgat, Wgat + 4096, Wgat + 8192, al, ar, 1, 0, 0, 1);
    gat_agg_k<<<ga, 256>>>(bgat);

    // ---- iteration 1 ----
    gemm_k<<<gg, 128>>>(nullptr, nullptr, nullptr,
                        Wc[0] + 4096, Wc[1] + 4096, Wc[2] + 4096, nullptr, nullptr, 1, 1, 1, 0);
    gcn_agg_k<<<ga, 256>>>(bc[0] + 64, bc[1] + 64, bc[2] + 64, 1);
    // it=1: s_f<-tro(Wx5), g_f<-sro(Wx3), t_f<-gro(Wx4)
    cross_k<<<1, 192>>>(Wx, bx, Wgat, al, 2, 0, 1, 5, 3, 4);
    gemm_k<<<gg, 128>>>(nullptr, nullptr, nullptr,
                        Wgat, Wgat + 4096, Wgat + 8192, al, ar, 1, 0, 0, 1);
    gat_agg_k<<<ga, 256>>>(bgat);

    // ---- final layer (readout only; no g_x write) ----
    gemm_k<<<gg, 128>>>(nullptr, nullptr, nullptr,
                        Wc[0] + 8192, Wc[1] + 8192, Wc[2] + 8192, nullptr, nullptr, 1, 1, 1, 0);
    gcn_agg_k<<<ga, 256>>>(bc[0] + 128, bc[1] + 128, bc[2] + 128, 0);
    mlp_k<<<1, 384>>>(W1, b1, W2, b2, W3, b3, out);
}

// round 7
// speedup vs baseline: 1.3171x; 1.0259x over previous
#include <cuda_runtime.h>
#include <cuda_fp16.h>

#define NN 50000
#define EE 800000

typedef unsigned long long u64;

// ---------------- scratch (static device globals; no allocation) ----------------
__device__ int       g_deg[3][2][NN];     // [graph][0=in,1=out]  (returned to 0 by scan_k)
__device__ int       g_rowptr[3][NN + 1];
__device__ int       g_cursor[3][NN];
__device__ int       g_col[3][EE];
__device__ float     g_no[3][NN];
__device__ float     g_ni[3][NN];
__device__ __half    g_h[3][NN * 64];     // GEMM output, fp16 (gather source)
__device__ float     g_x[3][NN * 64];     // node feature ping-pong buffer (fp32)
__device__ float     g_el[3][NN];
__device__ float     g_er[3][NN];
__device__ float     g_rosum[3][64];
__device__ unsigned  g_romax[3][64];
__device__ float     g_hsup[3][64];
__device__ float     g_elsup[3];

__device__ __forceinline__ u64 fma2(u64 a, u64 b, u64 c) {
    u64 d;
    asm("fma.rn.f32x2 %0, %1, %2, %3;" : "=l"(d) : "l"(a), "l"(b), "l"(c));
    return d;
}
__device__ __forceinline__ u64 dupf(float w) {
    u64 r;
    asm("mov.b64 %0, {%1, %1};" : "=l"(r) : "f"(w));
    return r;
}
__device__ __forceinline__ float f2lo(u64 v) { return __uint_as_float((unsigned)v); }
__device__ __forceinline__ float f2hi(u64 v) { return __uint_as_float((unsigned)(v >> 32)); }

__device__ __forceinline__ float lrelu(float x) { return x > 0.f ? x : 0.2f * x; }

// accumulate 4 fp16 channels (uint2) into float4 acc, optionally weighted
__device__ __forceinline__ void acc4(float4& a, uint2 v) {
    float2 f0 = __half22float2(*(const __half2*)&v.x);
    float2 f1 = __half22float2(*(const __half2*)&v.y);
    a.x += f0.x; a.y += f0.y; a.z += f1.x; a.w += f1.y;
}
__device__ __forceinline__ void acc4w(float4& a, uint2 v, float w) {
    float2 f0 = __half22float2(*(const __half2*)&v.x);
    float2 f1 = __half22float2(*(const __half2*)&v.y);
    a.x = fmaf(w, f0.x, a.x); a.y = fmaf(w, f0.y, a.y);
    a.z = fmaf(w, f1.x, a.z); a.w = fmaf(w, f1.y, a.w);
}

// ---------------- CSR build ----------------
__global__ void hist_k(const int* __restrict__ s0, const int* __restrict__ d0,
                       const int* __restrict__ s1, const int* __restrict__ d1,
                       const int* __restrict__ s2, const int* __restrict__ d2) {
    int q = blockIdx.y;
    const int* S = (q == 0) ? s0 : (q == 1) ? s1 : s2;
    const int* D = (q == 0) ? d0 : (q == 1) ? d1 : d2;
    int i = blockIdx.x * blockDim.x + threadIdx.x;
    if (i < EE) {
        atomicAdd(&g_deg[q][0][D[i]], 1);
        atomicAdd(&g_deg[q][1][S[i]], 1);
    }
}

__global__ void scan_k() {
    int q = blockIdx.x, t = threadIdx.x, lane = t & 31, w = t >> 5;
    __shared__ int wsum[32];
    __shared__ int stot;
    int carry = 0;
    for (int base = 0; base < NN; base += 1024) {
        int i = base + t;
        int v = (i < NN) ? g_deg[q][0][i] : 0;
        int x = v;
        #pragma unroll
        for (int o = 1; o < 32; o <<= 1) {
            int y = __shfl_up_sync(0xffffffffu, x, o);
            if (lane >= o) x += y;
        }
        if (lane == 31) wsum[w] = x;
        __syncthreads();
        if (w == 0) {
            int s = wsum[lane], sx = s;
            #pragma unroll
            for (int o = 1; o < 32; o <<= 1) {
                int y = __shfl_up_sync(0xffffffffu, sx, o);
                if (lane >= o) sx += y;
            }
            wsum[lane] = sx - s;
            if (lane == 31) stot = sx;
        }
        __syncthreads();
        int excl = carry + wsum[w] + x - v;
        if (i < NN) { g_rowptr[q][i] = excl; g_cursor[q][i] = excl; }
        carry += stot;
        __syncthreads();
    }
    if (t == 0) g_rowptr[q][NN] = carry;
    for (int i = t; i < NN; i += 1024) {
        int di = g_deg[q][0][i], dq = g_deg[q][1][i];
        g_ni[q][i] = rsqrtf((float)(di + 1));
        g_no[q][i] = rsqrtf((float)(dq + 1));
        g_deg[q][0][i] = 0;
        g_deg[q][1][i] = 0;
    }
}

__global__ void fill_k(const int* __restrict__ s0, const int* __restrict__ d0,
                       const int* __restrict__ s1, const int* __restrict__ d1,
                       const int* __restrict__ s2, const int* __restrict__ d2) {
    int q = blockIdx.y;
    const int* S = (q == 0) ? s0 : (q == 1) ? s1 : s2;
    const int* D = (q == 0) ? d0 : (q == 1) ? d1 : d2;
    int i = blockIdx.x * blockDim.x + threadIdx.x;
    if (i < EE) {
        int p = atomicAdd(&g_cursor[q][D[i]], 1);
        g_col[q][p] = S[i];
    }
}

// ---------------- GEMM: g_h[q] = fp16( (X[q] @ W[q]) * optional no ) -------------
// 128 threads, block tile 128 rows x 64 cols, thread tile 8x8, f32x2 row-pair accs.
__global__ void __launch_bounds__(128) gemm_k(
    const float* __restrict__ X0, const float* __restrict__ X1, const float* __restrict__ X2,
    const float* __restrict__ W0, const float* __restrict__ W1, const float* __restrict__ W2,
    const float* __restrict__ al, const float* __restrict__ ar,
    int srcIsGx, int useNorm, int zeroRO, int doEl) {
    int q = blockIdx.y;
    const float* X = srcIsGx ? g_x[q] : ((q == 0) ? X0 : (q == 1) ? X1 : X2);
    const float* W = (q == 0) ? W0 : (q == 1) ? W1 : W2;
    __shared__ float Xs[64][130];   // [k][row] transposed, 128 rows + pad
    __shared__ float Ws[64][64];    // [k][col]
    int t = threadIdx.x;
    if (zeroRO && blockIdx.x == 0 && t < 64) { g_rosum[q][t] = 0.f; g_romax[q][t] = 0u; }
    int row0 = blockIdx.x * 128;
    #pragma unroll
    for (int i = 0; i < 8; i++) {
        int idx = t + i * 128;                 // float4 index 0..1023
        float4 wv = *(const float4*)&W[idx * 4];
        int k = (idx * 4) >> 6, c = (idx * 4) & 63;
        *(float4*)&Ws[k][c] = wv;
    }
    #pragma unroll
    for (int i = 0; i < 16; i++) {
        int idx = t + i * 128;                 // 0..2047
        int r = idx >> 4, k4 = idx & 15;       // row 0..127, k-quad 0..15
        int row = row0 + r;
        float4 v = (row < NN) ? *(const float4*)&X[row * 64 + k4 * 4]
                              : make_float4(0.f, 0.f, 0.f, 0.f);
        Xs[k4 * 4 + 0][r] = v.x;
        Xs[k4 * 4 + 1][r] = v.y;
        Xs[k4 * 4 + 2][r] = v.z;
        Xs[k4 * 4 + 3][r] = v.w;
    }
    __syncthreads();

    int tx = t & 7;          // col group: cols c0..c0+7
    int ty = t >> 3;         // row group: rows r0..r0+7
    int c0 = tx * 8;
    int r0 = ty * 8;
    u64 acc[4][8];
    #pragma unroll
    for (int j = 0; j < 4; j++)
        #pragma unroll
        for (int c = 0; c < 8; c++) acc[j][c] = 0ull;

    #pragma unroll 8
    for (int k = 0; k < 64; k++) {
        u64 x0 = *(const u64*)&Xs[k][r0];
        u64 x1 = *(const u64*)&Xs[k][r0 + 2];
        u64 x2 = *(const u64*)&Xs[k][r0 + 4];
        u64 x3 = *(const u64*)&Xs[k][r0 + 6];
        float4 wa = *(const float4*)&Ws[k][c0];
        float4 wb = *(const float4*)&Ws[k][c0 + 4];
        u64 wd[8];
        wd[0] = dupf(wa.x); wd[1] = dupf(wa.y); wd[2] = dupf(wa.z); wd[3] = dupf(wa.w);
        wd[4] = dupf(wb.x); wd[5] = dupf(wb.y); wd[6] = dupf(wb.z); wd[7] = dupf(wb.w);
        #pragma unroll
        for (int c = 0; c < 8; c++) {
            acc[0][c] = fma2(x0, wd[c], acc[0][c]);
            acc[1][c] = fma2(x1, wd[c], acc[1][c]);
            acc[2][c] = fma2(x2, wd[c], acc[2][c]);
            acc[3][c] = fma2(x3, wd[c], acc[3][c]);
        }
    }

    int rbase = row0 + r0;
    float s[8];
    #pragma unroll
    for (int e = 0; e < 8; e++) s[e] = 1.f;
    if (useNorm) {
        #pragma unroll
        for (int e = 0; e < 8; e++) {
            int row = rbase + e;
            s[e] = (row < NN) ? g_no[q][row] : 1.f;
        }
    }
    __half* OUT = g_h[q];
    #pragma unroll
    for (int j = 0; j < 4; j++) {
        int rA = rbase + 2 * j, rB = rA + 1;
        if (rA < NN) {
            float sA = s[2 * j];
            __half2 p0 = __floats2half2_rn(f2lo(acc[j][0]) * sA, f2lo(acc[j][1]) * sA);
            __half2 p1 = __floats2half2_rn(f2lo(acc[j][2]) * sA, f2lo(acc[j][3]) * sA);
            __half2 p2 = __floats2half2_rn(f2lo(acc[j][4]) * sA, f2lo(acc[j][5]) * sA);
            __half2 p3 = __floats2half2_rn(f2lo(acc[j][6]) * sA, f2lo(acc[j][7]) * sA);
            uint4 pk = make_uint4(*(unsigned*)&p0, *(unsigned*)&p1,
                                  *(unsigned*)&p2, *(unsigned*)&p3);
            *(uint4*)&OUT[rA * 64 + c0] = pk;
        }
        if (rB < NN) {
            float sB = s[2 * j + 1];
            __half2 p0 = __floats2half2_rn(f2hi(acc[j][0]) * sB, f2hi(acc[j][1]) * sB);
            __half2 p1 = __floats2half2_rn(f2hi(acc[j][2]) * sB, f2hi(acc[j][3]) * sB);
            __half2 p2 = __floats2half2_rn(f2hi(acc[j][4]) * sB, f2hi(acc[j][5]) * sB);
            __half2 p3 = __floats2half2_rn(f2hi(acc[j][6]) * sB, f2hi(acc[j][7]) * sB);
            uint4 pk = make_uint4(*(unsigned*)&p0, *(unsigned*)&p1,
                                  *(unsigned*)&p2, *(unsigned*)&p3);
            *(uint4*)&OUT[rB * 64 + c0] = pk;
        }
    }
    if (doEl) {
        const float* alq = al + q * 64;
        const float* arq = ar + q * 64;
        float4 ala = *(const float4*)&alq[c0];
        float4 alb = *(const float4*)&alq[c0 + 4];
        float4 ara = *(const float4*)&arq[c0];
        float4 arb = *(const float4*)&arq[c0 + 4];
        float alv[8] = {ala.x, ala.y, ala.z, ala.w, alb.x, alb.y, alb.z, alb.w};
        float arv[8] = {ara.x, ara.y, ara.z, ara.w, arb.x, arb.y, arb.z, arb.w};
        #pragma unroll
        for (int j = 0; j < 4; j++) {
            u64 pl = 0ull, pr = 0ull;
            #pragma unroll
            for (int c = 0; c < 8; c++) {
                pl = fma2(acc[j][c], dupf(alv[c]), pl);
                pr = fma2(acc[j][c], dupf(arv[c]), pr);
            }
            float pl0 = f2lo(pl), pl1 = f2hi(pl);
            float pr0 = f2lo(pr), pr1 = f2hi(pr);
            #pragma unroll
            for (int o = 4; o; o >>= 1) {
                pl0 += __shfl_xor_sync(0xffffffffu, pl0, o, 8);
                pl1 += __shfl_xor_sync(0xffffffffu, pl1, o, 8);
                pr0 += __shfl_xor_sync(0xffffffffu, pr0, o, 8);
                pr1 += __shfl_xor_sync(0xffffffffu, pr1, o, 8);
            }
            int rA = rbase + 2 * j, rB = rA + 1;
            if (tx == 0) {
                if (rA < NN) { g_el[q][rA] = pl0; g_er[q][rA] = pr0; }
                if (rB < NN) { g_el[q][rB] = pl1; g_er[q][rB] = pr1; }
            }
        }
    }
}

// ---------------- GCN aggregation (2 edges/warp-step, uint2 loads) -> g_x --------
__global__ void __launch_bounds__(256) gcn_agg_k(
    const float* __restrict__ b0, const float* __restrict__ b1, const float* __restrict__ b2,
    int writeX) {
    int q = blockIdx.y;
    const float* bias = (q == 0) ? b0 : (q == 1) ? b1 : b2;
    int t = threadIdx.x, lane = t & 31, grp = t >> 5;
    int half = lane >> 4, ch = lane & 15;     // ch covers channels 4*ch..4*ch+3
    int d = blockIdx.x * 8 + grp;
    const uint2* __restrict__ hp = (const uint2*)g_h[q];   // 16 uint2 per row
    const int* __restrict__ col = g_col[q];
    float4 o = make_float4(0.f, 0.f, 0.f, 0.f);
    if (d < NN) {
        float4 a = make_float4(0.f, 0.f, 0.f, 0.f);
        if (half == 0) acc4(a, hp[d * 16 + ch]);     // self-loop (already * no[d])
        int s = g_rowptr[q][d], e = g_rowptr[q][d + 1];
        int i = s;
        for (; i + 8 <= e; i += 8) {
            int c0 = col[i + half],     c1 = col[i + 2 + half];
            int c2 = col[i + 4 + half], c3 = col[i + 6 + half];
            uint2 v0 = hp[c0 * 16 + ch];
            uint2 v1 = hp[c1 * 16 + ch];
            uint2 v2 = hp[c2 * 16 + ch];
            uint2 v3 = hp[c3 * 16 + ch];
            acc4(a, v0); acc4(a, v1); acc4(a, v2); acc4(a, v3);
        }
        for (; i < e; i += 2) {
            if (i + half < e) acc4(a, hp[col[i + half] * 16 + ch]);
        }
        // combine halves
        a.x += __shfl_xor_sync(0xffffffffu, a.x, 16);
        a.y += __shfl_xor_sync(0xffffffffu, a.y, 16);
        a.z += __shfl_xor_sync(0xffffffffu, a.z, 16);
        a.w += __shfl_xor_sync(0xffffffffu, a.w, 16);
        float ni = g_ni[q][d];
        float4 b = *(const float4*)&bias[4 * ch];
        o.x = fmaxf(fmaf(a.x, ni, b.x), 0.f);
        o.y = fmaxf(fmaf(a.y, ni, b.y), 0.f);
        o.z = fmaxf(fmaf(a.z, ni, b.z), 0.f);
        o.w = fmaxf(fmaf(a.w, ni, b.w), 0.f);
        if (writeX && half == 0)
            *(float4*)&g_x[q][d * 64 + 4 * ch] = o;
    }
    __shared__ float ssum[8][64];
    __shared__ float smax[8][64];
    if (half == 0) {
        *(float4*)&ssum[grp][4 * ch] = o;
        *(float4*)&smax[grp][4 * ch] = o;
    }
    __syncthreads();
    if (t < 64) {
        float s = 0.f, m = 0.f;
        #pragma unroll
        for (int g2 = 0; g2 < 8; g2++) { s += ssum[g2][t]; m = fmaxf(m, smax[g2][t]); }
        atomicAdd(&g_rosum[q][t], s);
        atomicMax(&g_romax[q][t], __float_as_uint(m));  // relu output >= 0: uint order ok
    }
}

// ---------------- cross features + supernode h/el ----------------
__global__ void cross_k(const float* __restrict__ Wx, const float* __restrict__ bx,
                        const float* __restrict__ Wg, const float* __restrict__ al,
                        int rg0, int rg1, int rg2, int wk0, int wk1, int wk2) {
    int t = threadIdx.x;           // 192
    int q = t >> 6, c = t & 63;
    int rg = (q == 0) ? rg0 : (q == 1) ? rg1 : rg2;
    int wk = (q == 0) ? wk0 : (q == 1) ? wk1 : wk2;
    __shared__ float fs[3][64];
    __shared__ float red[192];
    float acc = bx[wk * 64 + c];
    const float* wp = Wx + wk * 128 * 64;
    for (int j = 0; j < 128; j++) {
        float roj = (j < 64) ? g_rosum[rg][j] * (1.f / NN)
                             : __uint_as_float(g_romax[rg][j - 64]);
        acc = fmaf(roj, wp[j * 64 + c], acc);
    }
    fs[q][c] = fmaxf(acc, 0.f);
    __syncthreads();
    float hs = 0.f;
    const float* wg = Wg + q * 4096;
    for (int k = 0; k < 64; k++) hs = fmaf(fs[q][k], wg[k * 64 + c], hs);
    g_hsup[q][c] = hs;
    red[t] = hs * al[q * 64 + c];
    for (int o = 32; o >= 1; o >>= 1) {
        __syncthreads();
        if (c < o) red[t] += red[t + o];
    }
    if (c == 0) g_elsup[q] = red[t];
}

// ---------------- GAT aggregation: online softmax, 2 edges/warp-step -> g_x -----
__global__ void __launch_bounds__(256) gat_agg_k(const float* __restrict__ bgat) {
    int q = blockIdx.y;
    int t = threadIdx.x, lane = t & 31, grp = t >> 5;
    int half = lane >> 4, ch = lane & 15;
    int d = blockIdx.x * 8 + grp;
    __shared__ float sh_ee[8][32];
    __shared__ int   sh_c[8][32];
    if (d >= NN) return;
    const float* __restrict__ el = g_el[q];
    const uint2* __restrict__ hp = (const uint2*)g_h[q];
    const int* __restrict__ col = g_col[q];
    float erd = g_er[q][d];
    float e_self = lrelu(el[d] + erd);
    float e_sup  = lrelu(g_elsup[q] + erd);
    int s = g_rowptr[q][d], e = g_rowptr[q][d + 1];
    float m = -1e30f, ssum = 0.f;
    float4 a = make_float4(0.f, 0.f, 0.f, 0.f);
    for (int base = s; base < e; base += 32) {
        int i = base + lane;
        int cnt = min(32, e - base);
        int c = (i < e) ? col[i] : 0;
        float ei = (i < e) ? lrelu(el[c] + erd) : -1e30f;
        float cm = ei;
        #pragma unroll
        for (int o = 16; o; o >>= 1) cm = fmaxf(cm, __shfl_xor_sync(0xffffffffu, cm, o));
        float m2 = fmaxf(m, cm);
        float sc = expf(m - m2);
        a.x *= sc; a.y *= sc; a.z *= sc; a.w *= sc; ssum *= sc;
        m = m2;
        __syncwarp();
        sh_ee[grp][lane] = (i < e) ? expf(ei - m2) : 0.f;
        sh_c[grp][lane] = c;
        __syncwarp();
        int j = 0;
        for (; j + 8 <= cnt; j += 8) {
            float e0 = sh_ee[grp][j + half],     e1 = sh_ee[grp][j + 2 + half];
            float e2 = sh_ee[grp][j + 4 + half], e3 = sh_ee[grp][j + 6 + half];
            int c0 = sh_c[grp][j + half],     c1 = sh_c[grp][j + 2 + half];
            int c2 = sh_c[grp][j + 4 + half], c3 = sh_c[grp][j + 6 + half];
            uint2 v0 = hp[c0 * 16 + ch];
            uint2 v1 = hp[c1 * 16 + ch];
            uint2 v2 = hp[c2 * 16 + ch];
            uint2 v3 = hp[c3 * 16 + ch];
            acc4w(a, v0, e0); acc4w(a, v1, e1); acc4w(a, v2, e2); acc4w(a, v3, e3);
            ssum += (e0 + e1) + (e2 + e3);
        }
        for (; j < cnt; j += 2) {
            int jj = j + half;
            if (jj < cnt) {
                float e0 = sh_ee[grp][jj];
                acc4w(a, hp[sh_c[grp][jj] * 16 + ch], e0);
                ssum += e0;
            }
        }
    }
    // fold self-loop (half 0) + supernode edge (half 1)
    float m2 = fmaxf(m, fmaxf(e_self, e_sup));
    float sc = expf(m - m2);
    a.x *= sc; a.y *= sc; a.z *= sc; a.w *= sc; ssum *= sc;
    if (half == 0) {
        float ee = expf(e_self - m2);
        acc4w(a, hp[d * 16 + ch], ee);
        ssum += ee;
    } else {
        float ee = expf(e_sup - m2);
        float4 v = *(const float4*)&g_hsup[q][4 * ch];
        a.x = fmaf(ee, v.x, a.x); a.y = fmaf(ee, v.y, a.y);
        a.z = fmaf(ee, v.z, a.z); a.w = fmaf(ee, v.w, a.w);
        ssum += ee;
    }
    // combine halves
    a.x += __shfl_xor_sync(0xffffffffu, a.x, 16);
    a.y += __shfl_xor_sync(0xffffffffu, a.y, 16);
    a.z += __shfl_xor_sync(0xffffffffu, a.z, 16);
    a.w += __shfl_xor_sync(0xffffffffu, a.w, 16);
    ssum += __shfl_xor_sync(0xffffffffu, ssum, 16);
    if (half == 0) {
        float inv = 1.f / ssum;
        float4 b = *(const float4*)&bgat[q * 64 + 4 * ch];
        *(float4*)&g_x[q][d * 64 + 4 * ch] =
            make_float4(a.x * inv + b.x, a.y * inv + b.y,
                        a.z * inv + b.z, a.w * inv + b.w);
    }
}

// ---------------- final MLP + log_softmax ----------------
__global__ void mlp_k(const float* __restrict__ W1, const float* __restrict__ b1,
                      const float* __restrict__ W2, const float* __restrict__ b2,
                      const float* __restrict__ W3, const float* __restrict__ b3,
                      float* __restrict__ out) {
    __shared__ float nf[384], h1[192], h2[96], z[2];
    int t = threadIdx.x;  // 384
    {
        int q = t / 128, j = t % 128;
        nf[t] = (j < 64) ? g_rosum[q][j] * (1.f / NN)
                         : __uint_as_float(g_romax[q][j - 64]);
    }
    __syncthreads();
    if (t < 192) {
        float a = b1[t];
        for (int j = 0; j < 384; j++) a = fmaf(nf[j], W1[j * 192 + t], a);
        h1[t] = fmaxf(a, 0.f);
    }
    __syncthreads();
    if (t < 96) {
        float a = b2[t];
        for (int j = 0; j < 192; j++) a = fmaf(h1[j], W2[j * 96 + t], a);
        h2[t] = fmaxf(a, 0.f);
    }
    __syncthreads();
    if (t < 2) {
        float a = b3[t];
        for (int j = 0; j < 96; j++) a = fmaf(h2[j], W3[j * 2 + t], a);
        z[t] = a;
    }
    __syncthreads();
    if (t == 0) {
        float mm = fmaxf(z[0], z[1]);
        float l = mm + logf(expf(z[0] - mm) + expf(z[1] - mm));
        out[0] = z[0] - l;
        out[1] = z[1] - l;
    }
}

// ---------------- launch ----------------
extern "C" void kernel_launch(void* const* d_in, const int* in_sizes, int n_in,
                              void* d_out, int out_size) {
    (void)in_sizes; (void)n_in; (void)out_size;
    // allow 4 blocks/SM for the 50KB-smem gemm (idempotent; no allocation)
    cudaFuncSetAttribute((const void*)gemm_k,
                         cudaFuncAttributePreferredSharedMemoryCarveout, 100);
    const float* x0 = (const float*)d_in[0];
    const float* x1 = (const float*)d_in[1];
    const float* x2 = (const float*)d_in[2];
    const float* Wc[3] = {(const float*)d_in[3], (const float*)d_in[5], (const float*)d_in[7]};
    const float* bc[3] = {(const float*)d_in[4], (const float*)d_in[6], (const float*)d_in[8]};
    const float* Wx   = (const float*)d_in[9];
    const float* bx   = (const float*)d_in[10];
    const float* Wgat = (const float*)d_in[11];
    const float* al   = (const float*)d_in[12];
    const float* ar   = (const float*)d_in[13];
    const float* bgat = (const float*)d_in[14];
    const float* W1 = (const float*)d_in[15];
    const float* b1 = (const float*)d_in[16];
    const float* W2 = (const float*)d_in[17];
    const float* b2 = (const float*)d_in[18];
    const float* W3 = (const float*)d_in[19];
    const float* b3 = (const float*)d_in[20];
    const int* s0 = (const int*)d_in[21];
    const int* d0 = (const int*)d_in[22];
    const int* s1 = (const int*)d_in[23];
    const int* d1 = (const int*)d_in[24];
    const int* s2 = (const int*)d_in[25];
    const int* d2 = (const int*)d_in[26];
    float* out = (float*)d_out;

    // CSR build (g_deg restored to zero by scan_k each call)
    dim3 ge((EE + 255) / 256, 3);
    hist_k<<<ge, 256>>>(s0, d0, s1, d1, s2, d2);
    scan_k<<<3, 1024>>>();
    fill_k<<<ge, 256>>>(s0, d0, s1, d1, s2, d2);

    dim3 gg((NN + 127) / 128, 3);   // gemm (128-row tiles)
    dim3 ga((NN + 7) / 8, 3);       // per-node warp kernels

    // ---- iteration 0 ----
    gemm_k<<<gg, 128>>>(x0, x1, x2, Wc[0], Wc[1], Wc[2], nullptr, nullptr, 0, 1, 1, 0);
    gcn_agg_k<<<ga, 256>>>(bc[0], bc[1], bc[2], 1);
    // it=0: s_f<-gro(Wx1), g_f<-tro(Wx0), t_f<-sro(Wx2)
    cross_k<<<1, 192>>>(Wx, bx, Wgat, al, 1, 2, 0, 1, 0, 2);
    gemm_k<<<gg, 128>>>(nullptr, nullptr, nullptr,
                        Wgat, Wgat + 4096, Wgat + 8192, al, ar, 1, 0, 0, 1);
    gat_agg_k<<<ga, 256>>>(bgat);

    // ---- iteration 1 ----
    gemm_k<<<gg, 128>>>(nullptr, nullptr, nullptr,
                        Wc[0] + 4096, Wc[1] + 4096, Wc[2] + 4096, nullptr, nullptr, 1, 1, 1, 0);
    gcn_agg_k<<<ga, 256>>>(bc[0] + 64, bc[1] + 64, bc[2] + 64, 1);
    // it=1: s_f<-tro(Wx5), g_f<-sro(Wx3), t_f<-gro(Wx4)
    cross_k<<<1, 192>>>(Wx, bx, Wgat, al, 2, 0, 1, 5, 3, 4);
    gemm_k<<<gg, 128>>>(nullptr, nullptr, nullptr,
                        Wgat, Wgat + 4096, Wgat + 8192, al, ar, 1, 0, 0, 1);
    gat_agg_k<<<ga, 256>>>(bgat);

    // ---- final layer (readout only; no g_x write) ----
    gemm_k<<<gg, 128>>>(nullptr, nullptr, nullptr,
                        Wc[0] + 8192, Wc[1] + 8192, Wc[2] + 8192, nullptr, nullptr, 1, 1, 1, 0);
    gcn_agg_k<<<ga, 256>>>(bc[0] + 128, bc[1] + 128, bc[2] + 128, 0);
    mlp_k<<<1, 384>>>(W1, b1, W2, b2, W3, b3, out);
}